// round 13
// baseline (speedup 1.0000x reference)
#include <cuda_runtime.h>
#include <cuda_fp16.h>
#include <math.h>
#include <cstdint>

// ===========================================================================
// 3-stage video-Swin decoder. C=256, windows (2,8,8)=128 tokens.
// Dense GEMMs: fp16 HMMA, 128x128 CTA / 32x64 warp tile, BK=64, 3-stage
// cp.async pipeline, 2 CTAs/SM. Attention: fp16 HMMA, 256 thr / 16x128 warps.
// ===========================================================================

#define MAXTOK 131072
#define GEMM_SMEM (3 * 32768)

// ---- scratch (static device globals; no runtime allocation allowed) ----
__device__ float g_h  [(size_t)MAXTOK * 256];
__device__ float g_big[(size_t)65536 * 512];
__device__ __half g_a  [(size_t)MAXTOK * 256];
__device__ __half g_hid[(size_t)MAXTOK * 1024];
__device__ __half g_qh [(size_t)MAXTOK * 768];

#define WOFF_QKV(i)  ((size_t)(i) * 196608)
#define WOFF_PROJ(i) (1179648u + (size_t)(i) * 65536)
#define WOFF_MLP1(i) (1572864u + (size_t)(i) * 262144)
#define WOFF_MLP2(i) (3145728u + (size_t)(i) * 262144)
#define WOFF_EXPV    4718592u
#define WOFF_EXPT    4849664u
#define WTOT         4980736u
__device__ __half g_whi[WTOT];

// ===========================================================================
// PTX helpers
// ===========================================================================
__device__ __forceinline__ uint32_t smem_u32(const void* p) {
    uint32_t a;
    asm("{ .reg .u64 t; cvta.to.shared.u64 t, %1; cvt.u32.u64 %0, t; }"
        : "=r"(a) : "l"(p));
    return a;
}
__device__ __forceinline__ void cpasync16(uint32_t s, const void* g) {
    asm volatile("cp.async.cg.shared.global [%0], [%1], 16;" :: "r"(s), "l"(g));
}
#define CP_COMMIT() asm volatile("cp.async.commit_group;" ::: "memory")
#define CP_WAIT1()  asm volatile("cp.async.wait_group 1;" ::: "memory")
#define CP_WAIT0()  asm volatile("cp.async.wait_group 0;" ::: "memory")

__device__ __forceinline__ void ldsm4(uint32_t (&r)[4], uint32_t addr) {
    asm volatile("ldmatrix.sync.aligned.m8n8.x4.shared.b16 {%0,%1,%2,%3}, [%4];"
        : "=r"(r[0]), "=r"(r[1]), "=r"(r[2]), "=r"(r[3]) : "r"(addr));
}
__device__ __forceinline__ void ldsm4t(uint32_t (&r)[4], uint32_t addr) {
    asm volatile("ldmatrix.sync.aligned.m8n8.x4.trans.shared.b16 {%0,%1,%2,%3}, [%4];"
        : "=r"(r[0]), "=r"(r[1]), "=r"(r[2]), "=r"(r[3]) : "r"(addr));
}
__device__ __forceinline__ void mma16816(float (&d)[4], const uint32_t (&a)[4],
                                         uint32_t b0, uint32_t b1) {
    asm volatile(
        "mma.sync.aligned.m16n8k16.row.col.f32.f16.f16.f32 "
        "{%0,%1,%2,%3}, {%4,%5,%6,%7}, {%8,%9}, {%0,%1,%2,%3};"
        : "+f"(d[0]), "+f"(d[1]), "+f"(d[2]), "+f"(d[3])
        : "r"(a[0]), "r"(a[1]), "r"(a[2]), "r"(a[3]), "r"(b0), "r"(b1));
}
__device__ __forceinline__ uint32_t SW(uint32_t o) { return o ^ ((o >> 3) & 0x70); }

// ===========================================================================
// misc helpers
// ===========================================================================
__device__ __forceinline__ void st_h2(__half* __restrict__ dst, size_t idx,
                                      float a, float b) {
    *(half2*)(dst + idx) = __floats2half2_rn(a, b);
}
__device__ __forceinline__ void st_h4(__half* __restrict__ dst, size_t idx, float4 v) {
    *(half2*)(dst + idx)     = __floats2half2_rn(v.x, v.y);
    *(half2*)(dst + idx + 2) = __floats2half2_rn(v.z, v.w);
}
__device__ __forceinline__ float gelu_exact(float x) {
    return 0.5f * x * (1.f + erff(x * 0.70710678118654752f));
}

// windowed token -> source row in [B,D,64,64]
__device__ __forceinline__ size_t win_src_row(int tok, int D, int shifted) {
    int loc = tok & 127, win = tok >> 7;
    int ld = loc >> 6, lh = (loc >> 3) & 7, lw = loc & 7;
    int nWinB = (D >> 1) << 6;
    int b = win / nWinB;
    int wr = win - b * nWinB;
    int wd = wr >> 6, wh = (wr >> 3) & 7, ww = wr & 7;
    int gd = wd * 2 + ld, gh = wh * 8 + lh, gw = ww * 8 + lw;
    if (shifted) {
        gd += 1; if (gd >= D) gd -= D;
        gh = (gh + 4) & 63;
        gw = (gw + 4) & 63;
    }
    return ((size_t)(b * D + gd) << 12) + (size_t)(gh << 6) + (size_t)gw;
}

// ===========================================================================
// HMMA GEMM (unchanged round-9/10 core)
// OP 0: qkv -> fp16 (ld=N)              OP 1: proj scatter-add into h
// OP 2: GELU -> fp16 @1024              OP 3: add into h (ld=256)
// OP 4: store fp32 (ld=N; expands)      OP 5: OP3 + fp16 dual-store into oh
// ===========================================================================
__device__ __forceinline__ void load_chunk(
    uint32_t sbs, const __half* __restrict__ A, const __half* __restrict__ W,
    int bm, int bn, int K, int kc, int tid)
{
#pragma unroll
    for (int i = 0; i < 4; ++i) {
        int idx = i * 256 + tid;
        int row = idx >> 3, c = idx & 7;
        uint32_t o = SW((uint32_t)(row * 128 + c * 16));
        cpasync16(sbs + o, A + (size_t)(bm + row) * K + kc * 64 + c * 8);
    }
#pragma unroll
    for (int i = 0; i < 4; ++i) {
        int idx = i * 256 + tid;
        int row = idx >> 3, c = idx & 7;
        uint32_t o = SW((uint32_t)(row * 128 + c * 16));
        cpasync16(sbs + 16384 + o, W + (size_t)(bn + row) * K + kc * 64 + c * 8);
    }
}

template<int OP>
__global__ void __launch_bounds__(256, 2) mma_gemm(
    const __half* __restrict__ A, const __half* __restrict__ W,
    const float* __restrict__ bias,
    float* __restrict__ outf, __half* __restrict__ oh,
    int M, int N, int K, int Dd, int shifted)
{
    extern __shared__ char sm[];
    const uint32_t sb = smem_u32(sm);
    const int tid = threadIdx.x;
    const int lane = tid & 31;
    const int wid = tid >> 5;
    const int warpM = wid >> 1;
    const int warpN = wid & 1;
    const int bm = blockIdx.y * 128;
    const int bn = blockIdx.x * 128;
    const int NC = K >> 6;

    const uint32_t abase = (uint32_t)((warpM * 32 + (lane & 15)) * 128 + (lane >> 4) * 16);
    const uint32_t bbase = (uint32_t)((warpN * 64 + ((lane >> 4) * 8) + (lane & 7)) * 128 +
                                      ((lane >> 3) & 1) * 16);

    float acc[2][8][4];
#pragma unroll
    for (int mt = 0; mt < 2; ++mt)
#pragma unroll
        for (int nt = 0; nt < 8; ++nt)
#pragma unroll
            for (int r = 0; r < 4; ++r) acc[mt][nt][r] = 0.f;

    load_chunk(sb,         A, W, bm, bn, K, 0, tid);
    CP_COMMIT();
    if (NC > 1) load_chunk(sb + 32768, A, W, bm, bn, K, 1, tid);
    CP_COMMIT();

    int st = 0, ls = 2;
    for (int c = 0; c < NC; ++c) {
        CP_WAIT1();
        __syncthreads();
        uint32_t base = sb + st * 32768;
#pragma unroll
        for (int ks = 0; ks < 4; ++ks) {
            uint32_t ah[2][4], bh[8][2];
#pragma unroll
            for (int mt = 0; mt < 2; ++mt)
                ldsm4(ah[mt], base + SW(abase + mt * 2048 + ks * 32));
#pragma unroll
            for (int p = 0; p < 4; ++p) {
                uint32_t t[4];
                ldsm4(t, base + 16384 + SW(bbase + p * 2048 + ks * 32));
                bh[2*p][0] = t[0]; bh[2*p][1] = t[1];
                bh[2*p+1][0] = t[2]; bh[2*p+1][1] = t[3];
            }
#pragma unroll
            for (int mt = 0; mt < 2; ++mt)
#pragma unroll
                for (int nt = 0; nt < 8; ++nt)
                    mma16816(acc[mt][nt], ah[mt], bh[nt][0], bh[nt][1]);
        }
        int nc = c + 2;
        if (nc < NC)
            load_chunk(sb + ls * 32768, A, W, bm, bn, K, nc, tid);
        CP_COMMIT();
        st = (st == 2) ? 0 : st + 1;
        ls = (ls == 2) ? 0 : ls + 1;
    }

    const int lr = lane >> 2;
    const int lc = (lane & 3) * 2;
#pragma unroll
    for (int mt = 0; mt < 2; ++mt) {
        int r0 = bm + warpM * 32 + mt * 16 + lr;
        int r1 = r0 + 8;
        size_t ob0, ob1;
        if (OP == 1) {
            ob0 = win_src_row(r0, Dd, shifted) * 256;
            ob1 = win_src_row(r1, Dd, shifted) * 256;
        } else if (OP == 2) {
            ob0 = (size_t)r0 * 1024; ob1 = (size_t)r1 * 1024;
        } else if (OP == 3 || OP == 5) {
            ob0 = (size_t)r0 * 256;  ob1 = (size_t)r1 * 256;
        } else {
            ob0 = (size_t)r0 * N;    ob1 = (size_t)r1 * N;
        }
#pragma unroll
        for (int nt = 0; nt < 8; ++nt) {
            int col = bn + warpN * 64 + nt * 8 + lc;
            float v0 = acc[mt][nt][0], v1 = acc[mt][nt][1];
            float v2 = acc[mt][nt][2], v3 = acc[mt][nt][3];
            if (bias) {
                float b0 = bias[col], b1 = bias[col + 1];
                v0 += b0; v1 += b1; v2 += b0; v3 += b1;
            }
            if (OP == 0) {
                st_h2(oh, ob0 + col, v0, v1);
                st_h2(oh, ob1 + col, v2, v3);
            } else if (OP == 4) {
                *(float2*)(outf + ob0 + col) = make_float2(v0, v1);
                *(float2*)(outf + ob1 + col) = make_float2(v2, v3);
            } else if (OP == 1 || OP == 3 || OP == 5) {
                float2 o0 = *(float2*)(outf + ob0 + col);
                o0.x += v0; o0.y += v1;
                *(float2*)(outf + ob0 + col) = o0;
                float2 o1 = *(float2*)(outf + ob1 + col);
                o1.x += v2; o1.y += v3;
                *(float2*)(outf + ob1 + col) = o1;
                if (OP == 5) {
                    st_h2(oh, ob0 + col, o0.x, o0.y);
                    st_h2(oh, ob1 + col, o1.x, o1.y);
                }
            } else {
                st_h2(oh, ob0 + col, gelu_exact(v0), gelu_exact(v1));
                st_h2(oh, ob1 + col, gelu_exact(v2), gelu_exact(v3));
            }
        }
    }
}

// ===========================================================================
// HMMA window attention, 256 threads / 8 warps, warp tile 16x128.
// Halved accumulators -> <=128 regs -> 2 CTAs/SM = 16 warps.
// ===========================================================================
#define ASMEM 53248
#define A_Q  4096
#define A_K  20480
#define A_P0 4096
#define A_P1 20480
#define A_V  36864

__global__ void __launch_bounds__(256, 2) attn_mma_kernel(
    const __half* __restrict__ qkv, __half* __restrict__ out,
    const float* __restrict__ rpb, int D, int shifted)
{
    extern __shared__ char smc[];
    const uint32_t sb = smem_u32(smc);
    const int tid = threadIdx.x;
    const int lane = tid & 31;
    const int wid = tid >> 5;
    const int wbase = wid * 16;          // 16 rows per warp
    const int win = blockIdx.x;
    const int head = blockIdx.y;
    const size_t tokBase = (size_t)win * 128;

    float* rpbs = (float*)smc;
    int* clut = (int*)(smc + 2704);

    {
        const __half* ph = qkv + tokBase * 768 + head * 64;
#pragma unroll
        for (int i = 0; i < 4; ++i) {
            int idx = i * 256 + tid;
            int r = idx >> 3, c = idx & 7;
            uint32_t o = SW((uint32_t)(r * 128 + c * 16));
            size_t g = (size_t)r * 768 + c * 8;
            cpasync16(sb + A_Q + o, ph + g);
            cpasync16(sb + A_K + o, ph + 256 + g);
        }
        CP_COMMIT();
#pragma unroll
        for (int i = 0; i < 4; ++i) {
            int idx = i * 256 + tid;
            int r = idx >> 3, c = idx & 7;
            uint32_t o = SW((uint32_t)(r * 128 + c * 16));
            size_t g = (size_t)r * 768 + c * 8;
            cpasync16(sb + A_V + o, ph + 512 + g);
        }
        CP_COMMIT();
    }

    for (int i = tid; i < 675; i += 256) rpbs[i] = rpb[i * 4 + head];
    if (tid < 128) {
        int p = tid;
        int ld = p >> 6, lh = (p >> 3) & 7, lw = p & 7;
        int ct = ld * 225 + lh * 15 + lw;
        int nWinB = (D >> 1) << 6;
        int b = win / nWinB;
        int wr = win - b * nWinB;
        int wd = wr >> 6, wh = (wr >> 3) & 7, ww = wr & 7;
        int gd = wd * 2 + ld, gh2 = wh * 8 + lh, gw2 = ww * 8 + lw;
        int rd = (gd < D - 2) ? 0 : ((gd < D - 1) ? 1 : 2);
        int rh = (gh2 < 56) ? 0 : ((gh2 < 60) ? 1 : 2);
        int rw = (gw2 < 56) ? 0 : ((gw2 < 60) ? 1 : 2);
        clut[p] = ct | ((rd * 9 + rh * 3 + rw) << 16);
    }

    CP_WAIT1();
    __syncthreads();

    // ---- phase 1: S = q k^T  (warp tile 16x128) ----
    float acc[16][4];
#pragma unroll
    for (int nt = 0; nt < 16; ++nt)
#pragma unroll
        for (int r = 0; r < 4; ++r) acc[nt][r] = 0.f;

#pragma unroll
    for (int ks = 0; ks < 4; ++ks) {
        uint32_t aQ[4];
        {
            uint32_t o = (uint32_t)((wbase + (lane & 15)) * 128 +
                                    ks * 32 + (lane >> 4) * 16);
            ldsm4(aQ, sb + A_Q + SW(o));
        }
#pragma unroll
        for (int p4 = 0; p4 < 8; ++p4) {
            uint32_t o = (uint32_t)((p4 * 16 + (lane >> 4) * 8 + (lane & 7)) * 128 +
                                    ks * 32 + ((lane >> 3) & 1) * 16);
            uint32_t th[4];
            ldsm4(th, sb + A_K + SW(o));
            mma16816(acc[2*p4],   aQ, th[0], th[1]);
            mma16816(acc[2*p4+1], aQ, th[2], th[3]);
        }
    }

    // ---- bias + mask + softmax ----
    const int lr = lane >> 2;
    const int lc = lane & 3;
    float inv[2];
#pragma unroll
    for (int hh = 0; hh < 2; ++hh) {
        int row = wbase + hh * 8 + lr;
        int rv = clut[row];
        int basep = (rv & 0xffff) + 337;
        int rlab = rv >> 16;
        float mx = -1e30f;
#pragma unroll
        for (int nt = 0; nt < 16; ++nt)
#pragma unroll
            for (int e = 0; e < 2; ++e) {
                int cv = clut[nt * 8 + lc * 2 + e];
                float s = acc[nt][hh * 2 + e] * 0.125f +
                          rpbs[basep - (cv & 0xffff)];
                if (shifted && ((cv >> 16) != rlab)) s -= 100.f;
                acc[nt][hh * 2 + e] = s;
                mx = fmaxf(mx, s);
            }
        mx = fmaxf(mx, __shfl_xor_sync(0xffffffffu, mx, 1));
        mx = fmaxf(mx, __shfl_xor_sync(0xffffffffu, mx, 2));
        float sr = 0.f;
#pragma unroll
        for (int nt = 0; nt < 16; ++nt)
#pragma unroll
            for (int e = 0; e < 2; ++e) {
                float p = __expf(acc[nt][hh * 2 + e] - mx);
                acc[nt][hh * 2 + e] = p;
                sr += p;
            }
        sr += __shfl_xor_sync(0xffffffffu, sr, 1);
        sr += __shfl_xor_sync(0xffffffffu, sr, 2);
        inv[hh] = 1.f / sr;
    }

    __syncthreads();   // phase-1 smem reads done; P aliases Q/K region

#pragma unroll
    for (int hh = 0; hh < 2; ++hh) {
        int row = wbase + hh * 8 + lr;
#pragma unroll
        for (int nt = 0; nt < 16; ++nt) {
            float p0 = acc[nt][hh * 2];
            float p1 = acc[nt][hh * 2 + 1];
            uint32_t off = SW((uint32_t)(row * 128 + ((nt & 7) * 8 + lc * 2) * 2));
            uint32_t pbase = (nt < 8) ? A_P0 : A_P1;
            *(half2*)(smc + pbase + off) = __floats2half2_rn(p0, p1);
        }
    }
    CP_WAIT0();
    __syncthreads();

    // ---- phase 2: O = P V ----
    float oa[8][4];
#pragma unroll
    for (int nt = 0; nt < 8; ++nt)
#pragma unroll
        for (int r = 0; r < 4; ++r) oa[nt][r] = 0.f;

#pragma unroll
    for (int kc = 0; kc < 2; ++kc)
#pragma unroll
        for (int ks = 0; ks < 4; ++ks) {
            uint32_t aP[4];
            {
                uint32_t o = (uint32_t)((wbase + (lane & 15)) * 128 +
                                        ks * 32 + (lane >> 4) * 16);
                ldsm4(aP, sb + (kc ? A_P1 : A_P0) + SW(o));
            }
#pragma unroll
            for (int p4 = 0; p4 < 4; ++p4) {
                uint32_t o = (uint32_t)((kc * 64 + ks * 16 + (lane & 15)) * 128 +
                                        p4 * 32 + (lane >> 4) * 16);
                uint32_t th[4];
                ldsm4t(th, sb + A_V + SW(o));
                mma16816(oa[2*p4],   aP, th[0], th[1]);
                mma16816(oa[2*p4+1], aP, th[2], th[3]);
            }
        }

#pragma unroll
    for (int hh = 0; hh < 2; ++hh) {
        int row = wbase + hh * 8 + lr;
        size_t ob = (tokBase + row) * 256 + head * 64;
#pragma unroll
        for (int nt = 0; nt < 8; ++nt) {
            float v0 = oa[nt][hh * 2] * inv[hh];
            float v1 = oa[nt][hh * 2 + 1] * inv[hh];
            st_h2(out, ob + nt * 8 + lc * 2, v0, v1);
        }
    }
}

// ===========================================================================
// Batched weight transpose to fp16 [N,K]; LayerNorms (256 thr, 8 tok/blk)
// ===========================================================================
__global__ void __launch_bounds__(256) wconv_kernel(
    const float* __restrict__ W, __half* __restrict__ hi, int K, int N,
    size_t stride)
{
    W  += (size_t)blockIdx.z * stride;
    hi += (size_t)blockIdx.z * stride;
    __shared__ float t[32][33];
    int n0 = blockIdx.x * 32, k0 = blockIdx.y * 32;
    int tx = threadIdx.x & 31, ty = threadIdx.x >> 5;
    for (int i = ty; i < 32; i += 8)
        t[i][tx] = W[(size_t)(k0 + i) * N + n0 + tx];
    __syncthreads();
    for (int i = ty; i < 32; i += 8)
        hi[(size_t)(n0 + i) * K + k0 + tx] = __float2half_rn(t[tx][i]);
}

__device__ __forceinline__ void warp_ln_core(
    const float* __restrict__ src, const float* __restrict__ gw,
    const float* __restrict__ gb, int lane, float4& r0, float4& r1)
{
    const float4* xin = (const float4*)src;
    float4 v0 = xin[lane], v1 = xin[lane + 32];
    float s = v0.x + v0.y + v0.z + v0.w + v1.x + v1.y + v1.z + v1.w;
    float q = v0.x*v0.x + v0.y*v0.y + v0.z*v0.z + v0.w*v0.w +
              v1.x*v1.x + v1.y*v1.y + v1.z*v1.z + v1.w*v1.w;
#pragma unroll
    for (int off = 16; off; off >>= 1) {
        s += __shfl_xor_sync(0xffffffffu, s, off);
        q += __shfl_xor_sync(0xffffffffu, q, off);
    }
    float mu = s * (1.f / 256.f);
    float var = q * (1.f / 256.f) - mu * mu;
    float rs = rsqrtf(var + 1e-5f);
    const float4* g4 = (const float4*)gw;
    const float4* b4 = (const float4*)gb;
    float4 g0 = g4[lane], g1 = g4[lane + 32];
    float4 c0 = b4[lane], c1 = b4[lane + 32];
    r0.x = (v0.x - mu) * rs * g0.x + c0.x;
    r0.y = (v0.y - mu) * rs * g0.y + c0.y;
    r0.z = (v0.z - mu) * rs * g0.z + c0.z;
    r0.w = (v0.w - mu) * rs * g0.w + c0.w;
    r1.x = (v1.x - mu) * rs * g1.x + c1.x;
    r1.y = (v1.y - mu) * rs * g1.y + c1.y;
    r1.z = (v1.z - mu) * rs * g1.z + c1.z;
    r1.w = (v1.w - mu) * rs * g1.w + c1.w;
}

__global__ void __launch_bounds__(256) ln_gather_kernel(
    const float* __restrict__ h, __half* __restrict__ o,
    const float* __restrict__ gw, const float* __restrict__ gb,
    int D, int shifted)
{
    int tok = (blockIdx.x << 3) + (threadIdx.x >> 5);
    int lane = threadIdx.x & 31;
    size_t src = win_src_row(tok, D, shifted) * 256;
    float4 r0, r1;
    warp_ln_core(h + src, gw, gb, lane, r0, r1);
    size_t ob = (size_t)tok * 256 + lane * 4;
    st_h4(o, ob, r0);
    st_h4(o, ob + 128, r1);
}

__global__ void __launch_bounds__(256) ln_plain_kernel(
    const float* __restrict__ h, __half* __restrict__ o,
    const float* __restrict__ gw, const float* __restrict__ gb)
{
    int tok = (blockIdx.x << 3) + (threadIdx.x >> 5);
    int lane = threadIdx.x & 31;
    float4 r0, r1;
    warp_ln_core(h + (size_t)tok * 256, gw, gb, lane, r0, r1);
    size_t ob = (size_t)tok * 256 + lane * 4;
    st_h4(o, ob, r0);
    st_h4(o, ob + 128, r1);
}

__global__ void __launch_bounds__(256) expand_ln_kernel(
    const float* __restrict__ src, float* __restrict__ dst,
    const float* __restrict__ gw, const float* __restrict__ gb,
    int mode, int B, int T, int V)
{
    int tok = (blockIdx.x << 3) + (threadIdx.x >> 5);
    int lane = threadIdx.x & 31;
    int l = tok & 4095;
    int r = tok >> 12;
    int srow, e;
    if (mode == 0) {
        int V2 = V * 2;
        int v2 = r % V2; r /= V2;
        int t = r % T;   int b = r / T;
        e = v2 & 1;
        srow = ((b * T + t) * V + (v2 >> 1)) * 4096 + l;
    } else {
        int vv = r % V;  r /= V;
        int T2 = T * 2;
        int t2 = r % T2; int b = r / T2;
        e = t2 & 1;
        srow = ((b * T + (t2 >> 1)) * V + vv) * 4096 + l;
    }
    float4 r0, r1;
    warp_ln_core(src + (size_t)srow * 512 + e * 256, gw, gb, lane, r0, r1);
    float4* o = (float4*)(dst + (size_t)tok * 256);
    o[lane] = r0;
    o[lane + 32] = r1;
}

// ===========================================================================
// Host orchestration
// ===========================================================================
struct Bufs {
    float *h, *big;
    __half *a, *hid, *qh, *whi;
};

static void run_block(int i, int D, int shifted, const Bufs& B,
                      const float* n1w, const float* n1b,
                      const float* qkv_b, const float* rpb,
                      const float* proj_b, const float* n2w, const float* n2b,
                      const float* mlp1_b, const float* mlp2_b,
                      bool skip_front, bool dual)
{
    const int nTok = 2 * D * 4096;
    const int nWin = nTok / 128;

    if (!skip_front) {
        ln_gather_kernel<<<nTok / 8, 256>>>(B.h, B.a, n1w + i * 256, n1b + i * 256, D, shifted);
        mma_gemm<0><<<dim3(6, nTok / 128), 256, GEMM_SMEM>>>(
            B.a, B.whi + WOFF_QKV(i),
            qkv_b + i * 768, nullptr, B.qh, nTok, 768, 256, 0, 0);
        attn_mma_kernel<<<dim3(nWin, 4), 256, ASMEM>>>(
            B.qh, B.a, rpb + (size_t)i * 2700, D, shifted);
        mma_gemm<1><<<dim3(2, nTok / 128), 256, GEMM_SMEM>>>(
            B.a, B.whi + WOFF_PROJ(i),
            proj_b + i * 256, B.h, nullptr, nTok, 256, 256, D, shifted);
    }
    ln_plain_kernel<<<nTok / 8, 256>>>(B.h, B.a, n2w + i * 256, n2b + i * 256);
    mma_gemm<2><<<dim3(8, nTok / 128), 256, GEMM_SMEM>>>(
        B.a, B.whi + WOFF_MLP1(i),
        mlp1_b + i * 1024, nullptr, B.hid, nTok, 1024, 256, 0, 0);
    if (dual)
        mma_gemm<5><<<dim3(2, nTok / 128), 256, GEMM_SMEM>>>(
            B.hid, B.whi + WOFF_MLP2(i),
            mlp2_b + i * 256, B.h, B.a, nTok, 256, 1024, 0, 0);
    else
        mma_gemm<3><<<dim3(2, nTok / 128), 256, GEMM_SMEM>>>(
            B.hid, B.whi + WOFF_MLP2(i),
            mlp2_b + i * 256, B.h, nullptr, nTok, 256, 1024, 0, 0);
}

extern "C" void kernel_launch(void* const* d_in, const int* in_sizes, int n_in,
                              void* d_out, int out_size)
{
    const float* x       = (const float*)d_in[0];
    const float* n1w     = (const float*)d_in[1];
    const float* n1b     = (const float*)d_in[2];
    const float* qkv_w   = (const float*)d_in[3];
    const float* qkv_b   = (const float*)d_in[4];
    const float* rpb     = (const float*)d_in[5];
    const float* proj_w  = (const float*)d_in[6];
    const float* proj_b  = (const float*)d_in[7];
    const float* n2w     = (const float*)d_in[8];
    const float* n2b     = (const float*)d_in[9];
    const float* mlp1_w  = (const float*)d_in[10];
    const float* mlp1_b  = (const float*)d_in[11];
    const float* mlp2_w  = (const float*)d_in[12];
    const float* mlp2_b  = (const float*)d_in[13];
    const float* exp_v_w = (const float*)d_in[14];
    const float* exp_v_nw= (const float*)d_in[15];
    const float* exp_v_nb= (const float*)d_in[16];
    const float* exp_t_w = (const float*)d_in[17];
    const float* exp_t_nw= (const float*)d_in[18];
    const float* exp_t_nb= (const float*)d_in[19];
    (void)in_sizes; (void)n_in; (void)out_size;

    Bufs B;
    cudaGetSymbolAddress((void**)&B.h,   g_h);
    cudaGetSymbolAddress((void**)&B.big, g_big);
    cudaGetSymbolAddress((void**)&B.a,   g_a);
    cudaGetSymbolAddress((void**)&B.hid, g_hid);
    cudaGetSymbolAddress((void**)&B.qh,  g_qh);
    cudaGetSymbolAddress((void**)&B.whi, g_whi);

    cudaFuncSetAttribute(mma_gemm<0>, cudaFuncAttributeMaxDynamicSharedMemorySize, GEMM_SMEM);
    cudaFuncSetAttribute(mma_gemm<1>, cudaFuncAttributeMaxDynamicSharedMemorySize, GEMM_SMEM);
    cudaFuncSetAttribute(mma_gemm<2>, cudaFuncAttributeMaxDynamicSharedMemorySize, GEMM_SMEM);
    cudaFuncSetAttribute(mma_gemm<3>, cudaFuncAttributeMaxDynamicSharedMemorySize, GEMM_SMEM);
    cudaFuncSetAttribute(mma_gemm<4>, cudaFuncAttributeMaxDynamicSharedMemorySize, GEMM_SMEM);
    cudaFuncSetAttribute(mma_gemm<5>, cudaFuncAttributeMaxDynamicSharedMemorySize, GEMM_SMEM);
    cudaFuncSetAttribute(attn_mma_kernel, cudaFuncAttributeMaxDynamicSharedMemorySize, ASMEM);

    // batched weight conversions; qkv GEMM + attention in the profiler window
    wconv_kernel<<<dim3(24, 8, 6), 256>>>(qkv_w,  B.whi + WOFF_QKV(0),  256, 768,  196608);
    wconv_kernel<<<dim3(8,  8, 6), 256>>>(proj_w, B.whi + WOFF_PROJ(0), 256, 256,  65536);
    cudaMemcpyAsync(B.h, x, (size_t)32768 * 256 * sizeof(float),
                    cudaMemcpyDeviceToDevice, 0);
    ln_gather_kernel<<<32768 / 8, 256>>>(B.h, B.a, n1w, n1b, 4, 0);
    mma_gemm<0><<<dim3(6, 32768 / 128), 256, GEMM_SMEM>>>(
        B.a, B.whi + WOFF_QKV(0), qkv_b, nullptr, B.qh, 32768, 768, 256, 0, 0);
    attn_mma_kernel<<<dim3(256, 4), 256, ASMEM>>>(B.qh, B.a, rpb, 4, 0);
    mma_gemm<1><<<dim3(2, 32768 / 128), 256, GEMM_SMEM>>>(
        B.a, B.whi + WOFF_PROJ(0), proj_b, B.h, nullptr, 32768, 256, 256, 4, 0);

    wconv_kernel<<<dim3(32, 8, 6), 256>>>(mlp1_w, B.whi + WOFF_MLP1(0), 256, 1024, 262144);
    wconv_kernel<<<dim3(8, 32, 6), 256>>>(mlp2_w, B.whi + WOFF_MLP2(0), 1024, 256, 262144);
    wconv_kernel<<<dim3(16, 8, 1), 256>>>(exp_v_w, B.whi + WOFF_EXPV, 256, 512, 0);
    wconv_kernel<<<dim3(16, 8, 1), 256>>>(exp_t_w, B.whi + WOFF_EXPT, 256, 512, 0);

    // ---- stage 1: D = 4 (front of block 0 already launched above) ----
    run_block(0, 4, 0, B, n1w, n1b, qkv_b, rpb, proj_b, n2w, n2b, mlp1_b, mlp2_b, true,  false);
    run_block(1, 4, 1, B, n1w, n1b, qkv_b, rpb, proj_b, n2w, n2b, mlp1_b, mlp2_b, false, true);

    // ---- view expand: 32768 -> 65536 ----
    mma_gemm<4><<<dim3(4, 32768 / 128), 256, GEMM_SMEM>>>(
        B.a, B.whi + WOFF_EXPV, nullptr, B.big, nullptr, 32768, 512, 256, 0, 0);
    expand_ln_kernel<<<65536 / 8, 256>>>(B.big, B.h, exp_v_nw, exp_v_nb, 0, 2, 2, 2);

    // ---- stage 2: D = 8 ----
    run_block(2, 8, 0, B, n1w, n1b, qkv_b, rpb, proj_b, n2w, n2b, mlp1_b, mlp2_b, false, false);
    run_block(3, 8, 1, B, n1w, n1b, qkv_b, rpb, proj_b, n2w, n2b, mlp1_b, mlp2_b, false, true);

    // ---- temporal expand: 65536 -> 131072 ----
    mma_gemm<4><<<dim3(4, 65536 / 128), 256, GEMM_SMEM>>>(
        B.a, B.whi + WOFF_EXPT, nullptr, B.big, nullptr, 65536, 512, 256, 0, 0);
    expand_ln_kernel<<<131072 / 8, 256>>>(B.big, B.h, exp_t_nw, exp_t_nb, 1, 2, 2, 4);

    // ---- stage 3: D = 16 ----
    run_block(4, 16, 0, B, n1w, n1b, qkv_b, rpb, proj_b, n2w, n2b, mlp1_b, mlp2_b, false, false);
    run_block(5, 16, 1, B, n1w, n1b, qkv_b, rpb, proj_b, n2w, n2b, mlp1_b, mlp2_b, false, false);

    cudaMemcpyAsync(d_out, B.h, (size_t)131072 * 256 * sizeof(float),
                    cudaMemcpyDeviceToDevice, 0);
}

// round 14
// speedup vs baseline: 1.0135x; 1.0135x over previous
#include <cuda_runtime.h>
#include <cuda_fp16.h>
#include <math.h>
#include <cstdint>

// ===========================================================================
// 3-stage video-Swin decoder. C=256, windows (2,8,8)=128 tokens.
// Dense GEMMs: fp16 HMMA, 128x128 CTA / 32x64 warp tile, BK=64, 3-stage
// cp.async pipeline, 2 CTAs/SM. Attention: plain fp16 HMMA (round-11 form).
// Expand path: GEMM -> fp16 -> LN (halved expand traffic).
// ===========================================================================

#define MAXTOK 131072
#define GEMM_SMEM (3 * 32768)

// ---- scratch (static device globals; no runtime allocation allowed) ----
__device__ float g_h  [(size_t)MAXTOK * 256];
__device__ __half g_a  [(size_t)MAXTOK * 256];
__device__ __half g_hid[(size_t)MAXTOK * 1024];   // mlp hidden / expand out
__device__ __half g_qh [(size_t)MAXTOK * 768];

#define WOFF_QKV(i)  ((size_t)(i) * 196608)
#define WOFF_PROJ(i) (1179648u + (size_t)(i) * 65536)
#define WOFF_MLP1(i) (1572864u + (size_t)(i) * 262144)
#define WOFF_MLP2(i) (3145728u + (size_t)(i) * 262144)
#define WOFF_EXPV    4718592u
#define WOFF_EXPT    4849664u
#define WTOT         4980736u
__device__ __half g_whi[WTOT];

// ===========================================================================
// PTX helpers
// ===========================================================================
__device__ __forceinline__ uint32_t smem_u32(const void* p) {
    uint32_t a;
    asm("{ .reg .u64 t; cvta.to.shared.u64 t, %1; cvt.u32.u64 %0, t; }"
        : "=r"(a) : "l"(p));
    return a;
}
__device__ __forceinline__ void cpasync16(uint32_t s, const void* g) {
    asm volatile("cp.async.cg.shared.global [%0], [%1], 16;" :: "r"(s), "l"(g));
}
#define CP_COMMIT() asm volatile("cp.async.commit_group;" ::: "memory")
#define CP_WAIT1()  asm volatile("cp.async.wait_group 1;" ::: "memory")
#define CP_WAIT0()  asm volatile("cp.async.wait_group 0;" ::: "memory")

__device__ __forceinline__ void ldsm4(uint32_t (&r)[4], uint32_t addr) {
    asm volatile("ldmatrix.sync.aligned.m8n8.x4.shared.b16 {%0,%1,%2,%3}, [%4];"
        : "=r"(r[0]), "=r"(r[1]), "=r"(r[2]), "=r"(r[3]) : "r"(addr));
}
__device__ __forceinline__ void ldsm4t(uint32_t (&r)[4], uint32_t addr) {
    asm volatile("ldmatrix.sync.aligned.m8n8.x4.trans.shared.b16 {%0,%1,%2,%3}, [%4];"
        : "=r"(r[0]), "=r"(r[1]), "=r"(r[2]), "=r"(r[3]) : "r"(addr));
}
__device__ __forceinline__ void mma16816(float (&d)[4], const uint32_t (&a)[4],
                                         uint32_t b0, uint32_t b1) {
    asm volatile(
        "mma.sync.aligned.m16n8k16.row.col.f32.f16.f16.f32 "
        "{%0,%1,%2,%3}, {%4,%5,%6,%7}, {%8,%9}, {%0,%1,%2,%3};"
        : "+f"(d[0]), "+f"(d[1]), "+f"(d[2]), "+f"(d[3])
        : "r"(a[0]), "r"(a[1]), "r"(a[2]), "r"(a[3]), "r"(b0), "r"(b1));
}
__device__ __forceinline__ uint32_t SW(uint32_t o) { return o ^ ((o >> 3) & 0x70); }

// ===========================================================================
// misc helpers
// ===========================================================================
__device__ __forceinline__ void st_h2(__half* __restrict__ dst, size_t idx,
                                      float a, float b) {
    *(half2*)(dst + idx) = __floats2half2_rn(a, b);
}
__device__ __forceinline__ void st_h4(__half* __restrict__ dst, size_t idx, float4 v) {
    *(half2*)(dst + idx)     = __floats2half2_rn(v.x, v.y);
    *(half2*)(dst + idx + 2) = __floats2half2_rn(v.z, v.w);
}
__device__ __forceinline__ float gelu_exact(float x) {
    return 0.5f * x * (1.f + erff(x * 0.70710678118654752f));
}

// windowed token -> source row in [B,D,64,64]
__device__ __forceinline__ size_t win_src_row(int tok, int D, int shifted) {
    int loc = tok & 127, win = tok >> 7;
    int ld = loc >> 6, lh = (loc >> 3) & 7, lw = loc & 7;
    int nWinB = (D >> 1) << 6;
    int b = win / nWinB;
    int wr = win - b * nWinB;
    int wd = wr >> 6, wh = (wr >> 3) & 7, ww = wr & 7;
    int gd = wd * 2 + ld, gh = wh * 8 + lh, gw = ww * 8 + lw;
    if (shifted) {
        gd += 1; if (gd >= D) gd -= D;
        gh = (gh + 4) & 63;
        gw = (gw + 4) & 63;
    }
    return ((size_t)(b * D + gd) << 12) + (size_t)(gh << 6) + (size_t)gw;
}

// ===========================================================================
// HMMA GEMM (round-9/10 core)
// OP 0: +bias?, store fp16 (ld=N)       OP 1: proj scatter-add into h
// OP 2: GELU -> fp16 @1024              OP 3: add into h (ld=256)
// OP 5: OP3 + fp16 dual-store into oh
// ===========================================================================
__device__ __forceinline__ void load_chunk(
    uint32_t sbs, const __half* __restrict__ A, const __half* __restrict__ W,
    int bm, int bn, int K, int kc, int tid)
{
#pragma unroll
    for (int i = 0; i < 4; ++i) {
        int idx = i * 256 + tid;
        int row = idx >> 3, c = idx & 7;
        uint32_t o = SW((uint32_t)(row * 128 + c * 16));
        cpasync16(sbs + o, A + (size_t)(bm + row) * K + kc * 64 + c * 8);
    }
#pragma unroll
    for (int i = 0; i < 4; ++i) {
        int idx = i * 256 + tid;
        int row = idx >> 3, c = idx & 7;
        uint32_t o = SW((uint32_t)(row * 128 + c * 16));
        cpasync16(sbs + 16384 + o, W + (size_t)(bn + row) * K + kc * 64 + c * 8);
    }
}

template<int OP>
__global__ void __launch_bounds__(256, 2) mma_gemm(
    const __half* __restrict__ A, const __half* __restrict__ W,
    const float* __restrict__ bias,
    float* __restrict__ outf, __half* __restrict__ oh,
    int M, int N, int K, int Dd, int shifted)
{
    extern __shared__ char sm[];
    const uint32_t sb = smem_u32(sm);
    const int tid = threadIdx.x;
    const int lane = tid & 31;
    const int wid = tid >> 5;
    const int warpM = wid >> 1;
    const int warpN = wid & 1;
    const int bm = blockIdx.y * 128;
    const int bn = blockIdx.x * 128;
    const int NC = K >> 6;

    const uint32_t abase = (uint32_t)((warpM * 32 + (lane & 15)) * 128 + (lane >> 4) * 16);
    const uint32_t bbase = (uint32_t)((warpN * 64 + ((lane >> 4) * 8) + (lane & 7)) * 128 +
                                      ((lane >> 3) & 1) * 16);

    float acc[2][8][4];
#pragma unroll
    for (int mt = 0; mt < 2; ++mt)
#pragma unroll
        for (int nt = 0; nt < 8; ++nt)
#pragma unroll
            for (int r = 0; r < 4; ++r) acc[mt][nt][r] = 0.f;

    load_chunk(sb,         A, W, bm, bn, K, 0, tid);
    CP_COMMIT();
    if (NC > 1) load_chunk(sb + 32768, A, W, bm, bn, K, 1, tid);
    CP_COMMIT();

    int st = 0, ls = 2;
    for (int c = 0; c < NC; ++c) {
        CP_WAIT1();
        __syncthreads();
        uint32_t base = sb + st * 32768;
#pragma unroll
        for (int ks = 0; ks < 4; ++ks) {
            uint32_t ah[2][4], bh[8][2];
#pragma unroll
            for (int mt = 0; mt < 2; ++mt)
                ldsm4(ah[mt], base + SW(abase + mt * 2048 + ks * 32));
#pragma unroll
            for (int p = 0; p < 4; ++p) {
                uint32_t t[4];
                ldsm4(t, base + 16384 + SW(bbase + p * 2048 + ks * 32));
                bh[2*p][0] = t[0]; bh[2*p][1] = t[1];
                bh[2*p+1][0] = t[2]; bh[2*p+1][1] = t[3];
            }
#pragma unroll
            for (int mt = 0; mt < 2; ++mt)
#pragma unroll
                for (int nt = 0; nt < 8; ++nt)
                    mma16816(acc[mt][nt], ah[mt], bh[nt][0], bh[nt][1]);
        }
        int nc = c + 2;
        if (nc < NC)
            load_chunk(sb + ls * 32768, A, W, bm, bn, K, nc, tid);
        CP_COMMIT();
        st = (st == 2) ? 0 : st + 1;
        ls = (ls == 2) ? 0 : ls + 1;
    }

    const int lr = lane >> 2;
    const int lc = (lane & 3) * 2;
#pragma unroll
    for (int mt = 0; mt < 2; ++mt) {
        int r0 = bm + warpM * 32 + mt * 16 + lr;
        int r1 = r0 + 8;
        size_t ob0, ob1;
        if (OP == 1) {
            ob0 = win_src_row(r0, Dd, shifted) * 256;
            ob1 = win_src_row(r1, Dd, shifted) * 256;
        } else if (OP == 2) {
            ob0 = (size_t)r0 * 1024; ob1 = (size_t)r1 * 1024;
        } else if (OP == 3 || OP == 5) {
            ob0 = (size_t)r0 * 256;  ob1 = (size_t)r1 * 256;
        } else {
            ob0 = (size_t)r0 * N;    ob1 = (size_t)r1 * N;
        }
#pragma unroll
        for (int nt = 0; nt < 8; ++nt) {
            int col = bn + warpN * 64 + nt * 8 + lc;
            float v0 = acc[mt][nt][0], v1 = acc[mt][nt][1];
            float v2 = acc[mt][nt][2], v3 = acc[mt][nt][3];
            if (bias) {
                float b0 = bias[col], b1 = bias[col + 1];
                v0 += b0; v1 += b1; v2 += b0; v3 += b1;
            }
            if (OP == 0) {
                st_h2(oh, ob0 + col, v0, v1);
                st_h2(oh, ob1 + col, v2, v3);
            } else if (OP == 1 || OP == 3 || OP == 5) {
                float2 o0 = *(float2*)(outf + ob0 + col);
                o0.x += v0; o0.y += v1;
                *(float2*)(outf + ob0 + col) = o0;
                float2 o1 = *(float2*)(outf + ob1 + col);
                o1.x += v2; o1.y += v3;
                *(float2*)(outf + ob1 + col) = o1;
                if (OP == 5) {
                    st_h2(oh, ob0 + col, o0.x, o0.y);
                    st_h2(oh, ob1 + col, o1.x, o1.y);
                }
            } else {
                st_h2(oh, ob0 + col, gelu_exact(v0), gelu_exact(v1));
                st_h2(oh, ob1 + col, gelu_exact(v2), gelu_exact(v3));
            }
        }
    }
}

// ===========================================================================
// HMMA window attention, plain fp16 (round-11 form: 128 threads, 4 warps)
// ===========================================================================
#define ASMEM 53248
#define A_Q  4096
#define A_K  20480
#define A_P0 4096
#define A_P1 20480
#define A_V  36864

__global__ void __launch_bounds__(128, 2) attn_mma_kernel(
    const __half* __restrict__ qkv, __half* __restrict__ out,
    const float* __restrict__ rpb, int D, int shifted)
{
    extern __shared__ char smc[];
    const uint32_t sb = smem_u32(smc);
    const int tid = threadIdx.x;
    const int lane = tid & 31;
    const int wid = tid >> 5;
    const int wbase = wid * 32;
    const int win = blockIdx.x;
    const int head = blockIdx.y;
    const size_t tokBase = (size_t)win * 128;

    float* rpbs = (float*)smc;
    int* clut = (int*)(smc + 2704);

    {
        const __half* ph = qkv + tokBase * 768 + head * 64;
#pragma unroll
        for (int i = 0; i < 8; ++i) {
            int idx = i * 128 + tid;
            int r = idx >> 3, c = idx & 7;
            uint32_t o = SW((uint32_t)(r * 128 + c * 16));
            size_t g = (size_t)r * 768 + c * 8;
            cpasync16(sb + A_Q + o, ph + g);
            cpasync16(sb + A_K + o, ph + 256 + g);
        }
        CP_COMMIT();
#pragma unroll
        for (int i = 0; i < 8; ++i) {
            int idx = i * 128 + tid;
            int r = idx >> 3, c = idx & 7;
            uint32_t o = SW((uint32_t)(r * 128 + c * 16));
            size_t g = (size_t)r * 768 + c * 8;
            cpasync16(sb + A_V + o, ph + 512 + g);
        }
        CP_COMMIT();
    }

    for (int i = tid; i < 675; i += 128) rpbs[i] = rpb[i * 4 + head];
    {
        int p = tid;
        int ld = p >> 6, lh = (p >> 3) & 7, lw = p & 7;
        int ct = ld * 225 + lh * 15 + lw;
        int nWinB = (D >> 1) << 6;
        int b = win / nWinB;
        int wr = win - b * nWinB;
        int wd = wr >> 6, wh = (wr >> 3) & 7, ww = wr & 7;
        int gd = wd * 2 + ld, gh2 = wh * 8 + lh, gw2 = ww * 8 + lw;
        int rd = (gd < D - 2) ? 0 : ((gd < D - 1) ? 1 : 2);
        int rh = (gh2 < 56) ? 0 : ((gh2 < 60) ? 1 : 2);
        int rw = (gw2 < 56) ? 0 : ((gw2 < 60) ? 1 : 2);
        clut[p] = ct | ((rd * 9 + rh * 3 + rw) << 16);
    }

    CP_WAIT1();
    __syncthreads();

    // ---- phase 1: S = q k^T ----
    float acc[2][16][4];
#pragma unroll
    for (int mt = 0; mt < 2; ++mt)
#pragma unroll
        for (int nt = 0; nt < 16; ++nt)
#pragma unroll
            for (int r = 0; r < 4; ++r) acc[mt][nt][r] = 0.f;

#pragma unroll
    for (int ks = 0; ks < 4; ++ks) {
        uint32_t aQ[2][4];
#pragma unroll
        for (int mt = 0; mt < 2; ++mt) {
            uint32_t o = (uint32_t)((wbase + mt * 16 + (lane & 15)) * 128 +
                                    ks * 32 + (lane >> 4) * 16);
            ldsm4(aQ[mt], sb + A_Q + SW(o));
        }
#pragma unroll
        for (int p4 = 0; p4 < 8; ++p4) {
            uint32_t o = (uint32_t)((p4 * 16 + (lane >> 4) * 8 + (lane & 7)) * 128 +
                                    ks * 32 + ((lane >> 3) & 1) * 16);
            uint32_t th[4];
            ldsm4(th, sb + A_K + SW(o));
#pragma unroll
            for (int mt = 0; mt < 2; ++mt) {
                mma16816(acc[mt][2*p4],   aQ[mt], th[0], th[1]);
                mma16816(acc[mt][2*p4+1], aQ[mt], th[2], th[3]);
            }
        }
    }

    // ---- bias + mask + softmax ----
    const int lr = lane >> 2;
    const int lc = lane & 3;
    int clv[16][2];
#pragma unroll
    for (int nt = 0; nt < 16; ++nt) {
        clv[nt][0] = clut[nt * 8 + lc * 2];
        clv[nt][1] = clut[nt * 8 + lc * 2 + 1];
    }
    float inv[4];
#pragma unroll
    for (int ri = 0; ri < 4; ++ri) {
        int mt = ri >> 1, hh = ri & 1;
        int row = wbase + mt * 16 + hh * 8 + lr;
        int rv = clut[row];
        int basep = (rv & 0xffff) + 337;
        int rlab = rv >> 16;
        float mx = -1e30f;
#pragma unroll
        for (int nt = 0; nt < 16; ++nt)
#pragma unroll
            for (int e = 0; e < 2; ++e) {
                float s = acc[mt][nt][hh * 2 + e] * 0.125f +
                          rpbs[basep - (clv[nt][e] & 0xffff)];
                if (shifted && ((clv[nt][e] >> 16) != rlab)) s -= 100.f;
                acc[mt][nt][hh * 2 + e] = s;
                mx = fmaxf(mx, s);
            }
        mx = fmaxf(mx, __shfl_xor_sync(0xffffffffu, mx, 1));
        mx = fmaxf(mx, __shfl_xor_sync(0xffffffffu, mx, 2));
        float sr = 0.f;
#pragma unroll
        for (int nt = 0; nt < 16; ++nt)
#pragma unroll
            for (int e = 0; e < 2; ++e) {
                float p = __expf(acc[mt][nt][hh * 2 + e] - mx);
                acc[mt][nt][hh * 2 + e] = p;
                sr += p;
            }
        sr += __shfl_xor_sync(0xffffffffu, sr, 1);
        sr += __shfl_xor_sync(0xffffffffu, sr, 2);
        inv[ri] = 1.f / sr;
    }

    __syncthreads();   // phase-1 smem reads done; P aliases Q/K region

#pragma unroll
    for (int ri = 0; ri < 4; ++ri) {
        int mt = ri >> 1, hh = ri & 1;
        int row = wbase + mt * 16 + hh * 8 + lr;
#pragma unroll
        for (int nt = 0; nt < 16; ++nt) {
            float p0 = acc[mt][nt][hh * 2];
            float p1 = acc[mt][nt][hh * 2 + 1];
            uint32_t off = SW((uint32_t)(row * 128 + ((nt & 7) * 8 + lc * 2) * 2));
            uint32_t pbase = (nt < 8) ? A_P0 : A_P1;
            *(half2*)(smc + pbase + off) = __floats2half2_rn(p0, p1);
        }
    }
    CP_WAIT0();
    __syncthreads();

    // ---- phase 2: O = P V ----
    float oa[2][8][4];
#pragma unroll
    for (int mt = 0; mt < 2; ++mt)
#pragma unroll
        for (int nt = 0; nt < 8; ++nt)
#pragma unroll
            for (int r = 0; r < 4; ++r) oa[mt][nt][r] = 0.f;

#pragma unroll
    for (int kc = 0; kc < 2; ++kc)
#pragma unroll
        for (int ks = 0; ks < 4; ++ks) {
            uint32_t aP[2][4];
#pragma unroll
            for (int mt = 0; mt < 2; ++mt) {
                uint32_t o = (uint32_t)((wbase + mt * 16 + (lane & 15)) * 128 +
                                        ks * 32 + (lane >> 4) * 16);
                ldsm4(aP[mt], sb + (kc ? A_P1 : A_P0) + SW(o));
            }
#pragma unroll
            for (int p4 = 0; p4 < 4; ++p4) {
                uint32_t o = (uint32_t)((kc * 64 + ks * 16 + (lane & 15)) * 128 +
                                        p4 * 32 + (lane >> 4) * 16);
                uint32_t th[4];
                ldsm4t(th, sb + A_V + SW(o));
#pragma unroll
                for (int mt = 0; mt < 2; ++mt) {
                    mma16816(oa[mt][2*p4],   aP[mt], th[0], th[1]);
                    mma16816(oa[mt][2*p4+1], aP[mt], th[2], th[3]);
                }
            }
        }

#pragma unroll
    for (int ri = 0; ri < 4; ++ri) {
        int mt = ri >> 1, hh = ri & 1;
        int row = wbase + mt * 16 + hh * 8 + lr;
        size_t ob = (tokBase + row) * 256 + head * 64;
#pragma unroll
        for (int nt = 0; nt < 8; ++nt) {
            float v0 = oa[mt][nt][hh * 2] * inv[ri];
            float v1 = oa[mt][nt][hh * 2 + 1] * inv[ri];
            st_h2(out, ob + nt * 8 + lc * 2, v0, v1);
        }
    }
}

// ===========================================================================
// Batched weight transpose; LayerNorms (round-11 128-thread forms)
// ===========================================================================
__global__ void __launch_bounds__(256) wconv_kernel(
    const float* __restrict__ W, __half* __restrict__ hi, int K, int N,
    size_t stride)
{
    W  += (size_t)blockIdx.z * stride;
    hi += (size_t)blockIdx.z * stride;
    __shared__ float t[32][33];
    int n0 = blockIdx.x * 32, k0 = blockIdx.y * 32;
    int tx = threadIdx.x & 31, ty = threadIdx.x >> 5;
    for (int i = ty; i < 32; i += 8)
        t[i][tx] = W[(size_t)(k0 + i) * N + n0 + tx];
    __syncthreads();
    for (int i = ty; i < 32; i += 8)
        hi[(size_t)(n0 + i) * K + k0 + tx] = __float2half_rn(t[tx][i]);
}

__device__ __forceinline__ void warp_ln_vals(
    float4 v0, float4 v1, const float* __restrict__ gw,
    const float* __restrict__ gb, int lane, float4& r0, float4& r1)
{
    float s = v0.x + v0.y + v0.z + v0.w + v1.x + v1.y + v1.z + v1.w;
    float q = v0.x*v0.x + v0.y*v0.y + v0.z*v0.z + v0.w*v0.w +
              v1.x*v1.x + v1.y*v1.y + v1.z*v1.z + v1.w*v1.w;
#pragma unroll
    for (int off = 16; off; off >>= 1) {
        s += __shfl_xor_sync(0xffffffffu, s, off);
        q += __shfl_xor_sync(0xffffffffu, q, off);
    }
    float mu = s * (1.f / 256.f);
    float var = q * (1.f / 256.f) - mu * mu;
    float rs = rsqrtf(var + 1e-5f);
    const float4* g4 = (const float4*)gw;
    const float4* b4 = (const float4*)gb;
    float4 g0 = g4[lane], g1 = g4[lane + 32];
    float4 c0 = b4[lane], c1 = b4[lane + 32];
    r0.x = (v0.x - mu) * rs * g0.x + c0.x;
    r0.y = (v0.y - mu) * rs * g0.y + c0.y;
    r0.z = (v0.z - mu) * rs * g0.z + c0.z;
    r0.w = (v0.w - mu) * rs * g0.w + c0.w;
    r1.x = (v1.x - mu) * rs * g1.x + c1.x;
    r1.y = (v1.y - mu) * rs * g1.y + c1.y;
    r1.z = (v1.z - mu) * rs * g1.z + c1.z;
    r1.w = (v1.w - mu) * rs * g1.w + c1.w;
}

__global__ void __launch_bounds__(128) ln_gather_kernel(
    const float* __restrict__ h, __half* __restrict__ o,
    const float* __restrict__ gw, const float* __restrict__ gb,
    int D, int shifted)
{
    int tok = (blockIdx.x << 2) + (threadIdx.x >> 5);
    int lane = threadIdx.x & 31;
    const float4* xin = (const float4*)(h + win_src_row(tok, D, shifted) * 256);
    float4 r0, r1;
    warp_ln_vals(xin[lane], xin[lane + 32], gw, gb, lane, r0, r1);
    size_t ob = (size_t)tok * 256 + lane * 4;
    st_h4(o, ob, r0);
    st_h4(o, ob + 128, r1);
}

__global__ void __launch_bounds__(128) ln_plain_kernel(
    const float* __restrict__ h, __half* __restrict__ o,
    const float* __restrict__ gw, const float* __restrict__ gb)
{
    int tok = (blockIdx.x << 2) + (threadIdx.x >> 5);
    int lane = threadIdx.x & 31;
    const float4* xin = (const float4*)(h + (size_t)tok * 256);
    float4 r0, r1;
    warp_ln_vals(xin[lane], xin[lane + 32], gw, gb, lane, r0, r1);
    size_t ob = (size_t)tok * 256 + lane * 4;
    st_h4(o, ob, r0);
    st_h4(o, ob + 128, r1);
}

// expand reorder + LN; src is fp16 (expand GEMM output @ld=512), dst fp32 h
__global__ void __launch_bounds__(128) expand_ln_kernel(
    const __half* __restrict__ src, float* __restrict__ dst,
    const float* __restrict__ gw, const float* __restrict__ gb,
    int mode, int B, int T, int V)
{
    int tok = (blockIdx.x << 2) + (threadIdx.x >> 5);
    int lane = threadIdx.x & 31;
    int l = tok & 4095;
    int r = tok >> 12;
    int srow, e;
    if (mode == 0) {
        int V2 = V * 2;
        int v2 = r % V2; r /= V2;
        int t = r % T;   int b = r / T;
        e = v2 & 1;
        srow = ((b * T + t) * V + (v2 >> 1)) * 4096 + l;
    } else {
        int vv = r % V;  r /= V;
        int T2 = T * 2;
        int t2 = r % T2; int b = r / T2;
        e = t2 & 1;
        srow = ((b * T + (t2 >> 1)) * V + vv) * 4096 + l;
    }
    const __half* s = src + (size_t)srow * 512 + e * 256;
    float4 v0, v1;
    {
        half2 a0 = *(const half2*)(s + lane * 4);
        half2 a1 = *(const half2*)(s + lane * 4 + 2);
        half2 b0 = *(const half2*)(s + 128 + lane * 4);
        half2 b1 = *(const half2*)(s + 128 + lane * 4 + 2);
        v0 = make_float4(__half2float(a0.x), __half2float(a0.y),
                         __half2float(a1.x), __half2float(a1.y));
        v1 = make_float4(__half2float(b0.x), __half2float(b0.y),
                         __half2float(b1.x), __half2float(b1.y));
    }
    float4 r0, r1;
    warp_ln_vals(v0, v1, gw, gb, lane, r0, r1);
    float4* o = (float4*)(dst + (size_t)tok * 256);
    o[lane] = r0;
    o[lane + 32] = r1;
}

// ===========================================================================
// Host orchestration
// ===========================================================================
struct Bufs {
    float *h;
    __half *a, *hid, *qh, *whi;
};

static void run_block(int i, int D, int shifted, const Bufs& B,
                      const float* n1w, const float* n1b,
                      const float* qkv_b, const float* rpb,
                      const float* proj_b, const float* n2w, const float* n2b,
                      const float* mlp1_b, const float* mlp2_b,
                      bool skip_front, bool dual)
{
    const int nTok = 2 * D * 4096;
    const int nWin = nTok / 128;

    if (!skip_front) {
        ln_gather_kernel<<<nTok / 4, 128>>>(B.h, B.a, n1w + i * 256, n1b + i * 256, D, shifted);
        mma_gemm<0><<<dim3(6, nTok / 128), 256, GEMM_SMEM>>>(
            B.a, B.whi + WOFF_QKV(i),
            qkv_b + i * 768, nullptr, B.qh, nTok, 768, 256, 0, 0);
        attn_mma_kernel<<<dim3(nWin, 4), 128, ASMEM>>>(
            B.qh, B.a, rpb + (size_t)i * 2700, D, shifted);
        mma_gemm<1><<<dim3(2, nTok / 128), 256, GEMM_SMEM>>>(
            B.a, B.whi + WOFF_PROJ(i),
            proj_b + i * 256, B.h, nullptr, nTok, 256, 256, D, shifted);
    }
    ln_plain_kernel<<<nTok / 4, 128>>>(B.h, B.a, n2w + i * 256, n2b + i * 256);
    mma_gemm<2><<<dim3(8, nTok / 128), 256, GEMM_SMEM>>>(
        B.a, B.whi + WOFF_MLP1(i),
        mlp1_b + i * 1024, nullptr, B.hid, nTok, 1024, 256, 0, 0);
    if (dual)
        mma_gemm<5><<<dim3(2, nTok / 128), 256, GEMM_SMEM>>>(
            B.hid, B.whi + WOFF_MLP2(i),
            mlp2_b + i * 256, B.h, B.a, nTok, 256, 1024, 0, 0);
    else
        mma_gemm<3><<<dim3(2, nTok / 128), 256, GEMM_SMEM>>>(
            B.hid, B.whi + WOFF_MLP2(i),
            mlp2_b + i * 256, B.h, nullptr, nTok, 256, 1024, 0, 0);
}

extern "C" void kernel_launch(void* const* d_in, const int* in_sizes, int n_in,
                              void* d_out, int out_size)
{
    const float* x       = (const float*)d_in[0];
    const float* n1w     = (const float*)d_in[1];
    const float* n1b     = (const float*)d_in[2];
    const float* qkv_w   = (const float*)d_in[3];
    const float* qkv_b   = (const float*)d_in[4];
    const float* rpb     = (const float*)d_in[5];
    const float* proj_w  = (const float*)d_in[6];
    const float* proj_b  = (const float*)d_in[7];
    const float* n2w     = (const float*)d_in[8];
    const float* n2b     = (const float*)d_in[9];
    const float* mlp1_w  = (const float*)d_in[10];
    const float* mlp1_b  = (const float*)d_in[11];
    const float* mlp2_w  = (const float*)d_in[12];
    const float* mlp2_b  = (const float*)d_in[13];
    const float* exp_v_w = (const float*)d_in[14];
    const float* exp_v_nw= (const float*)d_in[15];
    const float* exp_v_nb= (const float*)d_in[16];
    const float* exp_t_w = (const float*)d_in[17];
    const float* exp_t_nw= (const float*)d_in[18];
    const float* exp_t_nb= (const float*)d_in[19];
    (void)in_sizes; (void)n_in; (void)out_size;

    Bufs B;
    cudaGetSymbolAddress((void**)&B.h,   g_h);
    cudaGetSymbolAddress((void**)&B.a,   g_a);
    cudaGetSymbolAddress((void**)&B.hid, g_hid);
    cudaGetSymbolAddress((void**)&B.qh,  g_qh);
    cudaGetSymbolAddress((void**)&B.whi, g_whi);

    cudaFuncSetAttribute(mma_gemm<0>, cudaFuncAttributeMaxDynamicSharedMemorySize, GEMM_SMEM);
    cudaFuncSetAttribute(mma_gemm<1>, cudaFuncAttributeMaxDynamicSharedMemorySize, GEMM_SMEM);
    cudaFuncSetAttribute(mma_gemm<2>, cudaFuncAttributeMaxDynamicSharedMemorySize, GEMM_SMEM);
    cudaFuncSetAttribute(mma_gemm<3>, cudaFuncAttributeMaxDynamicSharedMemorySize, GEMM_SMEM);
    cudaFuncSetAttribute(mma_gemm<5>, cudaFuncAttributeMaxDynamicSharedMemorySize, GEMM_SMEM);
    cudaFuncSetAttribute(attn_mma_kernel, cudaFuncAttributeMaxDynamicSharedMemorySize, ASMEM);

    // batched weight conversions; qkv GEMM + attention in the profiler window
    wconv_kernel<<<dim3(24, 8, 6), 256>>>(qkv_w,  B.whi + WOFF_QKV(0),  256, 768,  196608);
    wconv_kernel<<<dim3(8,  8, 6), 256>>>(proj_w, B.whi + WOFF_PROJ(0), 256, 256,  65536);
    cudaMemcpyAsync(B.h, x, (size_t)32768 * 256 * sizeof(float),
                    cudaMemcpyDeviceToDevice, 0);
    ln_gather_kernel<<<32768 / 4, 128>>>(B.h, B.a, n1w, n1b, 4, 0);
    mma_gemm<0><<<dim3(6, 32768 / 128), 256, GEMM_SMEM>>>(
        B.a, B.whi + WOFF_QKV(0), qkv_b, nullptr, B.qh, 32768, 768, 256, 0, 0);
    attn_mma_kernel<<<dim3(256, 4), 128, ASMEM>>>(B.qh, B.a, rpb, 4, 0);
    mma_gemm<1><<<dim3(2, 32768 / 128), 256, GEMM_SMEM>>>(
        B.a, B.whi + WOFF_PROJ(0), proj_b, B.h, nullptr, 32768, 256, 256, 4, 0);

    wconv_kernel<<<dim3(32, 8, 6), 256>>>(mlp1_w, B.whi + WOFF_MLP1(0), 256, 1024, 262144);
    wconv_kernel<<<dim3(8, 32, 6), 256>>>(mlp2_w, B.whi + WOFF_MLP2(0), 1024, 256, 262144);
    wconv_kernel<<<dim3(16, 8, 1), 256>>>(exp_v_w, B.whi + WOFF_EXPV, 256, 512, 0);
    wconv_kernel<<<dim3(16, 8, 1), 256>>>(exp_t_w, B.whi + WOFF_EXPT, 256, 512, 0);

    // ---- stage 1: D = 4 (front of block 0 already launched above) ----
    run_block(0, 4, 0, B, n1w, n1b, qkv_b, rpb, proj_b, n2w, n2b, mlp1_b, mlp2_b, true,  false);
    run_block(1, 4, 1, B, n1w, n1b, qkv_b, rpb, proj_b, n2w, n2b, mlp1_b, mlp2_b, false, true);

    // ---- view expand: 32768 -> 65536 (fp16 GEMM out -> fp16 LN in) ----
    mma_gemm<0><<<dim3(4, 32768 / 128), 256, GEMM_SMEM>>>(
        B.a, B.whi + WOFF_EXPV, nullptr, nullptr, B.hid, 32768, 512, 256, 0, 0);
    expand_ln_kernel<<<65536 / 4, 128>>>(B.hid, B.h, exp_v_nw, exp_v_nb, 0, 2, 2, 2);

    // ---- stage 2: D = 8 ----
    run_block(2, 8, 0, B, n1w, n1b, qkv_b, rpb, proj_b, n2w, n2b, mlp1_b, mlp2_b, false, false);
    run_block(3, 8, 1, B, n1w, n1b, qkv_b, rpb, proj_b, n2w, n2b, mlp1_b, mlp2_b, false, true);

    // ---- temporal expand: 65536 -> 131072 ----
    mma_gemm<0><<<dim3(4, 65536 / 128), 256, GEMM_SMEM>>>(
        B.a, B.whi + WOFF_EXPT, nullptr, nullptr, B.hid, 65536, 512, 256, 0, 0);
    expand_ln_kernel<<<131072 / 4, 128>>>(B.hid, B.h, exp_t_nw, exp_t_nb, 1, 2, 2, 4);

    // ---- stage 3: D = 16 ----
    run_block(4, 16, 0, B, n1w, n1b, qkv_b, rpb, proj_b, n2w, n2b, mlp1_b, mlp2_b, false, false);
    run_block(5, 16, 1, B, n1w, n1b, qkv_b, rpb, proj_b, n2w, n2b, mlp1_b, mlp2_b, false, false);

    cudaMemcpyAsync(d_out, B.h, (size_t)131072 * 256 * sizeof(float),
                    cudaMemcpyDeviceToDevice, 0);
}

// round 16
// speedup vs baseline: 1.0198x; 1.0062x over previous
#include <cuda_runtime.h>
#include <cuda_fp16.h>
#include <math.h>
#include <cstdint>

// ===========================================================================
// 3-stage video-Swin decoder. C=256, windows (2,8,8)=128 tokens.
// Dense GEMMs: fp16 HMMA, 128x128 CTA / 32x64 warp tile, BK=64, 3-stage
// cp.async pipeline, 2 CTAs/SM. Attention: plain fp16 HMMA.
// This round: div-free window indexing (lg2 shifts), hoisted bias loads.
// ===========================================================================

#define MAXTOK 131072
#define GEMM_SMEM (3 * 32768)

// ---- scratch (static device globals; no runtime allocation allowed) ----
__device__ float g_h  [(size_t)MAXTOK * 256];
__device__ __half g_a  [(size_t)MAXTOK * 256];
__device__ __half g_hid[(size_t)MAXTOK * 1024];   // mlp hidden / expand out
__device__ __half g_qh [(size_t)MAXTOK * 768];

#define WOFF_QKV(i)  ((size_t)(i) * 196608)
#define WOFF_PROJ(i) (1179648u + (size_t)(i) * 65536)
#define WOFF_MLP1(i) (1572864u + (size_t)(i) * 262144)
#define WOFF_MLP2(i) (3145728u + (size_t)(i) * 262144)
#define WOFF_EXPV    4718592u
#define WOFF_EXPT    4849664u
#define WTOT         4980736u
__device__ __half g_whi[WTOT];

// ===========================================================================
// PTX helpers
// ===========================================================================
__device__ __forceinline__ uint32_t smem_u32(const void* p) {
    uint32_t a;
    asm("{ .reg .u64 t; cvta.to.shared.u64 t, %1; cvt.u32.u64 %0, t; }"
        : "=r"(a) : "l"(p));
    return a;
}
__device__ __forceinline__ void cpasync16(uint32_t s, const void* g) {
    asm volatile("cp.async.cg.shared.global [%0], [%1], 16;" :: "r"(s), "l"(g));
}
#define CP_COMMIT() asm volatile("cp.async.commit_group;" ::: "memory")
#define CP_WAIT1()  asm volatile("cp.async.wait_group 1;" ::: "memory")
#define CP_WAIT0()  asm volatile("cp.async.wait_group 0;" ::: "memory")

__device__ __forceinline__ void ldsm4(uint32_t (&r)[4], uint32_t addr) {
    asm volatile("ldmatrix.sync.aligned.m8n8.x4.shared.b16 {%0,%1,%2,%3}, [%4];"
        : "=r"(r[0]), "=r"(r[1]), "=r"(r[2]), "=r"(r[3]) : "r"(addr));
}
__device__ __forceinline__ void ldsm4t(uint32_t (&r)[4], uint32_t addr) {
    asm volatile("ldmatrix.sync.aligned.m8n8.x4.trans.shared.b16 {%0,%1,%2,%3}, [%4];"
        : "=r"(r[0]), "=r"(r[1]), "=r"(r[2]), "=r"(r[3]) : "r"(addr));
}
__device__ __forceinline__ void mma16816(float (&d)[4], const uint32_t (&a)[4],
                                         uint32_t b0, uint32_t b1) {
    asm volatile(
        "mma.sync.aligned.m16n8k16.row.col.f32.f16.f16.f32 "
        "{%0,%1,%2,%3}, {%4,%5,%6,%7}, {%8,%9}, {%0,%1,%2,%3};"
        : "+f"(d[0]), "+f"(d[1]), "+f"(d[2]), "+f"(d[3])
        : "r"(a[0]), "r"(a[1]), "r"(a[2]), "r"(a[3]), "r"(b0), "r"(b1));
}
__device__ __forceinline__ uint32_t SW(uint32_t o) { return o ^ ((o >> 3) & 0x70); }

// ===========================================================================
// misc helpers
// ===========================================================================
__device__ __forceinline__ void st_h2(__half* __restrict__ dst, size_t idx,
                                      float a, float b) {
    *(half2*)(dst + idx) = __floats2half2_rn(a, b);
}
__device__ __forceinline__ void st_h4(__half* __restrict__ dst, size_t idx, float4 v) {
    *(half2*)(dst + idx)     = __floats2half2_rn(v.x, v.y);
    *(half2*)(dst + idx + 2) = __floats2half2_rn(v.z, v.w);
}
__device__ __forceinline__ float gelu_exact(float x) {
    return 0.5f * x * (1.f + erff(x * 0.70710678118654752f));
}

// windowed token -> source row in [B,D,64,64].
// lg = log2((D/2)*64); division-free (nWinB is always a power of two).
__device__ __forceinline__ size_t win_src_row(int tok, int D, int lg, int shifted) {
    int loc = tok & 127, win = tok >> 7;
    int ld = loc >> 6, lh = (loc >> 3) & 7, lw = loc & 7;
    int b = win >> lg;
    int wr = win & ((1 << lg) - 1);
    int wd = wr >> 6, wh = (wr >> 3) & 7, ww = wr & 7;
    int gd = wd * 2 + ld, gh = wh * 8 + lh, gw = ww * 8 + lw;
    if (shifted) {
        gd += 1; if (gd >= D) gd -= D;
        gh = (gh + 4) & 63;
        gw = (gw + 4) & 63;
    }
    return ((size_t)(b * D + gd) << 12) + (size_t)(gh << 6) + (size_t)gw;
}

// ===========================================================================
// HMMA GEMM (round-9/10 core)
// OP 0: +bias?, store fp16 (ld=N)       OP 1: proj scatter-add into h
// OP 2: GELU -> fp16 @1024              OP 3: add into h (ld=256)
// OP 5: OP3 + fp16 dual-store into oh
// ===========================================================================
__device__ __forceinline__ void load_chunk(
    uint32_t sbs, const __half* __restrict__ A, const __half* __restrict__ W,
    int bm, int bn, int K, int kc, int tid)
{
#pragma unroll
    for (int i = 0; i < 4; ++i) {
        int idx = i * 256 + tid;
        int row = idx >> 3, c = idx & 7;
        uint32_t o = SW((uint32_t)(row * 128 + c * 16));
        cpasync16(sbs + o, A + (size_t)(bm + row) * K + kc * 64 + c * 8);
    }
#pragma unroll
    for (int i = 0; i < 4; ++i) {
        int idx = i * 256 + tid;
        int row = idx >> 3, c = idx & 7;
        uint32_t o = SW((uint32_t)(row * 128 + c * 16));
        cpasync16(sbs + 16384 + o, W + (size_t)(bn + row) * K + kc * 64 + c * 8);
    }
}

template<int OP>
__global__ void __launch_bounds__(256, 2) mma_gemm(
    const __half* __restrict__ A, const __half* __restrict__ W,
    const float* __restrict__ bias,
    float* __restrict__ outf, __half* __restrict__ oh,
    int M, int N, int K, int Dd, int lg, int shifted)
{
    extern __shared__ char sm[];
    const uint32_t sb = smem_u32(sm);
    const int tid = threadIdx.x;
    const int lane = tid & 31;
    const int wid = tid >> 5;
    const int warpM = wid >> 1;
    const int warpN = wid & 1;
    const int bm = blockIdx.y * 128;
    const int bn = blockIdx.x * 128;
    const int NC = K >> 6;

    const uint32_t abase = (uint32_t)((warpM * 32 + (lane & 15)) * 128 + (lane >> 4) * 16);
    const uint32_t bbase = (uint32_t)((warpN * 64 + ((lane >> 4) * 8) + (lane & 7)) * 128 +
                                      ((lane >> 3) & 1) * 16);

    float acc[2][8][4];
#pragma unroll
    for (int mt = 0; mt < 2; ++mt)
#pragma unroll
        for (int nt = 0; nt < 8; ++nt)
#pragma unroll
            for (int r = 0; r < 4; ++r) acc[mt][nt][r] = 0.f;

    load_chunk(sb,         A, W, bm, bn, K, 0, tid);
    CP_COMMIT();
    if (NC > 1) load_chunk(sb + 32768, A, W, bm, bn, K, 1, tid);
    CP_COMMIT();

    int st = 0, ls = 2;
    for (int c = 0; c < NC; ++c) {
        CP_WAIT1();
        __syncthreads();
        uint32_t base = sb + st * 32768;
#pragma unroll
        for (int ks = 0; ks < 4; ++ks) {
            uint32_t ah[2][4], bh[8][2];
#pragma unroll
            for (int mt = 0; mt < 2; ++mt)
                ldsm4(ah[mt], base + SW(abase + mt * 2048 + ks * 32));
#pragma unroll
            for (int p = 0; p < 4; ++p) {
                uint32_t t[4];
                ldsm4(t, base + 16384 + SW(bbase + p * 2048 + ks * 32));
                bh[2*p][0] = t[0]; bh[2*p][1] = t[1];
                bh[2*p+1][0] = t[2]; bh[2*p+1][1] = t[3];
            }
#pragma unroll
            for (int mt = 0; mt < 2; ++mt)
#pragma unroll
                for (int nt = 0; nt < 8; ++nt)
                    mma16816(acc[mt][nt], ah[mt], bh[nt][0], bh[nt][1]);
        }
        int nc = c + 2;
        if (nc < NC)
            load_chunk(sb + ls * 32768, A, W, bm, bn, K, nc, tid);
        CP_COMMIT();
        st = (st == 2) ? 0 : st + 1;
        ls = (ls == 2) ? 0 : ls + 1;
    }

    const int lr = lane >> 2;
    const int lc = (lane & 3) * 2;

    // hoisted bias (independent of mt)
    float bv[8][2];
    if (bias) {
#pragma unroll
        for (int nt = 0; nt < 8; ++nt) {
            int col = bn + warpN * 64 + nt * 8 + lc;
            bv[nt][0] = bias[col];
            bv[nt][1] = bias[col + 1];
        }
    } else {
#pragma unroll
        for (int nt = 0; nt < 8; ++nt) { bv[nt][0] = 0.f; bv[nt][1] = 0.f; }
    }

#pragma unroll
    for (int mt = 0; mt < 2; ++mt) {
        int r0 = bm + warpM * 32 + mt * 16 + lr;
        int r1 = r0 + 8;
        size_t ob0, ob1;
        if (OP == 1) {
            ob0 = win_src_row(r0, Dd, lg, shifted) * 256;
            ob1 = win_src_row(r1, Dd, lg, shifted) * 256;
        } else if (OP == 2) {
            ob0 = (size_t)r0 * 1024; ob1 = (size_t)r1 * 1024;
        } else if (OP == 3 || OP == 5) {
            ob0 = (size_t)r0 * 256;  ob1 = (size_t)r1 * 256;
        } else {
            ob0 = (size_t)r0 * N;    ob1 = (size_t)r1 * N;
        }
#pragma unroll
        for (int nt = 0; nt < 8; ++nt) {
            int col = bn + warpN * 64 + nt * 8 + lc;
            float v0 = acc[mt][nt][0] + bv[nt][0];
            float v1 = acc[mt][nt][1] + bv[nt][1];
            float v2 = acc[mt][nt][2] + bv[nt][0];
            float v3 = acc[mt][nt][3] + bv[nt][1];
            if (OP == 0) {
                st_h2(oh, ob0 + col, v0, v1);
                st_h2(oh, ob1 + col, v2, v3);
            } else if (OP == 1 || OP == 3 || OP == 5) {
                float2 o0 = *(float2*)(outf + ob0 + col);
                o0.x += v0; o0.y += v1;
                *(float2*)(outf + ob0 + col) = o0;
                float2 o1 = *(float2*)(outf + ob1 + col);
                o1.x += v2; o1.y += v3;
                *(float2*)(outf + ob1 + col) = o1;
                if (OP == 5) {
                    st_h2(oh, ob0 + col, o0.x, o0.y);
                    st_h2(oh, ob1 + col, o1.x, o1.y);
                }
            } else {
                st_h2(oh, ob0 + col, gelu_exact(v0), gelu_exact(v1));
                st_h2(oh, ob1 + col, gelu_exact(v2), gelu_exact(v3));
            }
        }
    }
}

// ===========================================================================
// HMMA window attention, plain fp16 (128 threads, 4 warps)
// ===========================================================================
#define ASMEM 53248
#define A_Q  4096
#define A_K  20480
#define A_P0 4096
#define A_P1 20480
#define A_V  36864

__global__ void __launch_bounds__(128, 2) attn_mma_kernel(
    const __half* __restrict__ qkv, __half* __restrict__ out,
    const float* __restrict__ rpb, int D, int lg, int shifted)
{
    extern __shared__ char smc[];
    const uint32_t sb = smem_u32(smc);
    const int tid = threadIdx.x;
    const int lane = tid & 31;
    const int wid = tid >> 5;
    const int wbase = wid * 32;
    const int win = blockIdx.x;
    const int head = blockIdx.y;
    const size_t tokBase = (size_t)win * 128;

    float* rpbs = (float*)smc;
    int* clut = (int*)(smc + 2704);

    {
        const __half* ph = qkv + tokBase * 768 + head * 64;
#pragma unroll
        for (int i = 0; i < 8; ++i) {
            int idx = i * 128 + tid;
            int r = idx >> 3, c = idx & 7;
            uint32_t o = SW((uint32_t)(r * 128 + c * 16));
            size_t g = (size_t)r * 768 + c * 8;
            cpasync16(sb + A_Q + o, ph + g);
            cpasync16(sb + A_K + o, ph + 256 + g);
        }
        CP_COMMIT();
#pragma unroll
        for (int i = 0; i < 8; ++i) {
            int idx = i * 128 + tid;
            int r = idx >> 3, c = idx & 7;
            uint32_t o = SW((uint32_t)(r * 128 + c * 16));
            size_t g = (size_t)r * 768 + c * 8;
            cpasync16(sb + A_V + o, ph + 512 + g);
        }
        CP_COMMIT();
    }

    for (int i = tid; i < 675; i += 128) rpbs[i] = rpb[i * 4 + head];
    {
        int p = tid;
        int ld = p >> 6, lh = (p >> 3) & 7, lw = p & 7;
        int ct = ld * 225 + lh * 15 + lw;
        int b = win >> lg;
        int wr = win & ((1 << lg) - 1);
        int wd = wr >> 6, wh = (wr >> 3) & 7, ww = wr & 7;
        int gd = wd * 2 + ld, gh2 = wh * 8 + lh, gw2 = ww * 8 + lw;
        (void)b;
        int rd = (gd < D - 2) ? 0 : ((gd < D - 1) ? 1 : 2);
        int rh = (gh2 < 56) ? 0 : ((gh2 < 60) ? 1 : 2);
        int rw = (gw2 < 56) ? 0 : ((gw2 < 60) ? 1 : 2);
        clut[p] = ct | ((rd * 9 + rh * 3 + rw) << 16);
    }

    CP_WAIT1();
    __syncthreads();

    // ---- phase 1: S = q k^T ----
    float acc[2][16][4];
#pragma unroll
    for (int mt = 0; mt < 2; ++mt)
#pragma unroll
        for (int nt = 0; nt < 16; ++nt)
#pragma unroll
            for (int r = 0; r < 4; ++r) acc[mt][nt][r] = 0.f;

#pragma unroll
    for (int ks = 0; ks < 4; ++ks) {
        uint32_t aQ[2][4];
#pragma unroll
        for (int mt = 0; mt < 2; ++mt) {
            uint32_t o = (uint32_t)((wbase + mt * 16 + (lane & 15)) * 128 +
                                    ks * 32 + (lane >> 4) * 16);
            ldsm4(aQ[mt], sb + A_Q + SW(o));
        }
#pragma unroll
        for (int p4 = 0; p4 < 8; ++p4) {
            uint32_t o = (uint32_t)((p4 * 16 + (lane >> 4) * 8 + (lane & 7)) * 128 +
                                    ks * 32 + ((lane >> 3) & 1) * 16);
            uint32_t th[4];
            ldsm4(th, sb + A_K + SW(o));
#pragma unroll
            for (int mt = 0; mt < 2; ++mt) {
                mma16816(acc[mt][2*p4],   aQ[mt], th[0], th[1]);
                mma16816(acc[mt][2*p4+1], aQ[mt], th[2], th[3]);
            }
        }
    }

    // ---- bias + mask + softmax ----
    const int lr = lane >> 2;
    const int lc = lane & 3;
    int clv[16][2];
#pragma unroll
    for (int nt = 0; nt < 16; ++nt) {
        clv[nt][0] = clut[nt * 8 + lc * 2];
        clv[nt][1] = clut[nt * 8 + lc * 2 + 1];
    }
    float inv[4];
#pragma unroll
    for (int ri = 0; ri < 4; ++ri) {
        int mt = ri >> 1, hh = ri & 1;
        int row = wbase + mt * 16 + hh * 8 + lr;
        int rv = clut[row];
        int basep = (rv & 0xffff) + 337;
        int rlab = rv >> 16;
        float mx = -1e30f;
#pragma unroll
        for (int nt = 0; nt < 16; ++nt)
#pragma unroll
            for (int e = 0; e < 2; ++e) {
                float s = acc[mt][nt][hh * 2 + e] * 0.125f +
                          rpbs[basep - (clv[nt][e] & 0xffff)];
                if (shifted && ((clv[nt][e] >> 16) != rlab)) s -= 100.f;
                acc[mt][nt][hh * 2 + e] = s;
                mx = fmaxf(mx, s);
            }
        mx = fmaxf(mx, __shfl_xor_sync(0xffffffffu, mx, 1));
        mx = fmaxf(mx, __shfl_xor_sync(0xffffffffu, mx, 2));
        float sr = 0.f;
#pragma unroll
        for (int nt = 0; nt < 16; ++nt)
#pragma unroll
            for (int e = 0; e < 2; ++e) {
                float p = __expf(acc[mt][nt][hh * 2 + e] - mx);
                acc[mt][nt][hh * 2 + e] = p;
                sr += p;
            }
        sr += __shfl_xor_sync(0xffffffffu, sr, 1);
        sr += __shfl_xor_sync(0xffffffffu, sr, 2);
        inv[ri] = 1.f / sr;
    }

    __syncthreads();   // phase-1 smem reads done; P aliases Q/K region

#pragma unroll
    for (int ri = 0; ri < 4; ++ri) {
        int mt = ri >> 1, hh = ri & 1;
        int row = wbase + mt * 16 + hh * 8 + lr;
#pragma unroll
        for (int nt = 0; nt < 16; ++nt) {
            float p0 = acc[mt][nt][hh * 2];
            float p1 = acc[mt][nt][hh * 2 + 1];
            uint32_t off = SW((uint32_t)(row * 128 + ((nt & 7) * 8 + lc * 2) * 2));
            uint32_t pbase = (nt < 8) ? A_P0 : A_P1;
            *(half2*)(smc + pbase + off) = __floats2half2_rn(p0, p1);
        }
    }
    CP_WAIT0();
    __syncthreads();

    // ---- phase 2: O = P V ----
    float oa[2][8][4];
#pragma unroll
    for (int mt = 0; mt < 2; ++mt)
#pragma unroll
        for (int nt = 0; nt < 8; ++nt)
#pragma unroll
            for (int r = 0; r < 4; ++r) oa[mt][nt][r] = 0.f;

#pragma unroll
    for (int kc = 0; kc < 2; ++kc)
#pragma unroll
        for (int ks = 0; ks < 4; ++ks) {
            uint32_t aP[2][4];
#pragma unroll
            for (int mt = 0; mt < 2; ++mt) {
                uint32_t o = (uint32_t)((wbase + mt * 16 + (lane & 15)) * 128 +
                                        ks * 32 + (lane >> 4) * 16);
                ldsm4(aP[mt], sb + (kc ? A_P1 : A_P0) + SW(o));
            }
#pragma unroll
            for (int p4 = 0; p4 < 4; ++p4) {
                uint32_t o = (uint32_t)((kc * 64 + ks * 16 + (lane & 15)) * 128 +
                                        p4 * 32 + (lane >> 4) * 16);
                uint32_t th[4];
                ldsm4t(th, sb + A_V + SW(o));
#pragma unroll
                for (int mt = 0; mt < 2; ++mt) {
                    mma16816(oa[mt][2*p4],   aP[mt], th[0], th[1]);
                    mma16816(oa[mt][2*p4+1], aP[mt], th[2], th[3]);
                }
            }
        }

#pragma unroll
    for (int ri = 0; ri < 4; ++ri) {
        int mt = ri >> 1, hh = ri & 1;
        int row = wbase + mt * 16 + hh * 8 + lr;
        size_t ob = (tokBase + row) * 256 + head * 64;
#pragma unroll
        for (int nt = 0; nt < 8; ++nt) {
            float v0 = oa[mt][nt][hh * 2] * inv[ri];
            float v1 = oa[mt][nt][hh * 2 + 1] * inv[ri];
            st_h2(out, ob + nt * 8 + lc * 2, v0, v1);
        }
    }
}

// ===========================================================================
// Batched weight transpose; LayerNorms
// ===========================================================================
__global__ void __launch_bounds__(256) wconv_kernel(
    const float* __restrict__ W, __half* __restrict__ hi, int K, int N,
    size_t stride)
{
    W  += (size_t)blockIdx.z * stride;
    hi += (size_t)blockIdx.z * stride;
    __shared__ float t[32][33];
    int n0 = blockIdx.x * 32, k0 = blockIdx.y * 32;
    int tx = threadIdx.x & 31, ty = threadIdx.x >> 5;
    for (int i = ty; i < 32; i += 8)
        t[i][tx] = W[(size_t)(k0 + i) * N + n0 + tx];
    __syncthreads();
    for (int i = ty; i < 32; i += 8)
        hi[(size_t)(n0 + i) * K + k0 + tx] = __float2half_rn(t[tx][i]);
}

__device__ __forceinline__ void warp_ln_vals(
    float4 v0, float4 v1, const float* __restrict__ gw,
    const float* __restrict__ gb, int lane, float4& r0, float4& r1)
{
    float s = v0.x + v0.y + v0.z + v0.w + v1.x + v1.y + v1.z + v1.w;
    float q = v0.x*v0.x + v0.y*v0.y + v0.z*v0.z + v0.w*v0.w +
              v1.x*v1.x + v1.y*v1.y + v1.z*v1.z + v1.w*v1.w;
#pragma unroll
    for (int off = 16; off; off >>= 1) {
        s += __shfl_xor_sync(0xffffffffu, s, off);
        q += __shfl_xor_sync(0xffffffffu, q, off);
    }
    float mu = s * (1.f / 256.f);
    float var = q * (1.f / 256.f) - mu * mu;
    float rs = rsqrtf(var + 1e-5f);
    const float4* g4 = (const float4*)gw;
    const float4* b4 = (const float4*)gb;
    float4 g0 = g4[lane], g1 = g4[lane + 32];
    float4 c0 = b4[lane], c1 = b4[lane + 32];
    r0.x = (v0.x - mu) * rs * g0.x + c0.x;
    r0.y = (v0.y - mu) * rs * g0.y + c0.y;
    r0.z = (v0.z - mu) * rs * g0.z + c0.z;
    r0.w = (v0.w - mu) * rs * g0.w + c0.w;
    r1.x = (v1.x - mu) * rs * g1.x + c1.x;
    r1.y = (v1.y - mu) * rs * g1.y + c1.y;
    r1.z = (v1.z - mu) * rs * g1.z + c1.z;
    r1.w = (v1.w - mu) * rs * g1.w + c1.w;
}

__global__ void __launch_bounds__(128) ln_gather_kernel(
    const float* __restrict__ h, __half* __restrict__ o,
    const float* __restrict__ gw, const float* __restrict__ gb,
    int D, int lg, int shifted)
{
    int tok = (blockIdx.x << 2) + (threadIdx.x >> 5);
    int lane = threadIdx.x & 31;
    const float4* xin = (const float4*)(h + win_src_row(tok, D, lg, shifted) * 256);
    float4 r0, r1;
    warp_ln_vals(xin[lane], xin[lane + 32], gw, gb, lane, r0, r1);
    size_t ob = (size_t)tok * 256 + lane * 4;
    st_h4(o, ob, r0);
    st_h4(o, ob + 128, r1);
}

__global__ void __launch_bounds__(128) ln_plain_kernel(
    const float* __restrict__ h, __half* __restrict__ o,
    const float* __restrict__ gw, const float* __restrict__ gb)
{
    int tok = (blockIdx.x << 2) + (threadIdx.x >> 5);
    int lane = threadIdx.x & 31;
    const float4* xin = (const float4*)(h + (size_t)tok * 256);
    float4 r0, r1;
    warp_ln_vals(xin[lane], xin[lane + 32], gw, gb, lane, r0, r1);
    size_t ob = (size_t)tok * 256 + lane * 4;
    st_h4(o, ob, r0);
    st_h4(o, ob + 128, r1);
}

// expand reorder + LN; src is fp16 (expand GEMM output @ld=512), dst fp32 h
__global__ void __launch_bounds__(128) expand_ln_kernel(
    const __half* __restrict__ src, float* __restrict__ dst,
    const float* __restrict__ gw, const float* __restrict__ gb,
    int mode, int B, int T, int V)
{
    int tok = (blockIdx.x << 2) + (threadIdx.x >> 5);
    int lane = threadIdx.x & 31;
    int l = tok & 4095;
    int r = tok >> 12;
    int srow, e;
    if (mode == 0) {
        int V2 = V * 2;
        int v2 = r % V2; r /= V2;
        int t = r % T;   int b = r / T;
        e = v2 & 1;
        srow = ((b * T + t) * V + (v2 >> 1)) * 4096 + l;
    } else {
        int vv = r % V;  r /= V;
        int T2 = T * 2;
        int t2 = r % T2; int b = r / T2;
        e = t2 & 1;
        srow = ((b * T + (t2 >> 1)) * V + vv) * 4096 + l;
    }
    const __half* s = src + (size_t)srow * 512 + e * 256;
    float4 v0, v1;
    {
        half2 a0 = *(const half2*)(s + lane * 4);
        half2 a1 = *(const half2*)(s + lane * 4 + 2);
        half2 b0 = *(const half2*)(s + 128 + lane * 4);
        half2 b1 = *(const half2*)(s + 128 + lane * 4 + 2);
        v0 = make_float4(__half2float(a0.x), __half2float(a0.y),
                         __half2float(a1.x), __half2float(a1.y));
        v1 = make_float4(__half2float(b0.x), __half2float(b0.y),
                         __half2float(b1.x), __half2float(b1.y));
    }
    float4 r0, r1;
    warp_ln_vals(v0, v1, gw, gb, lane, r0, r1);
    float4* o = (float4*)(dst + (size_t)tok * 256);
    o[lane] = r0;
    o[lane + 32] = r1;
}

// ===========================================================================
// Host orchestration
// ===========================================================================
struct Bufs {
    float *h;
    __half *a, *hid, *qh, *whi;
};

static inline int lg2_nwinb(int D) { return (D == 4) ? 7 : (D == 8) ? 8 : 9; }

static void run_block(int i, int D, int shifted, const Bufs& B,
                      const float* n1w, const float* n1b,
                      const float* qkv_b, const float* rpb,
                      const float* proj_b, const float* n2w, const float* n2b,
                      const float* mlp1_b, const float* mlp2_b,
                      bool skip_front, bool dual)
{
    const int nTok = 2 * D * 4096;
    const int nWin = nTok / 128;
    const int lg = lg2_nwinb(D);

    if (!skip_front) {
        ln_gather_kernel<<<nTok / 4, 128>>>(B.h, B.a, n1w + i * 256, n1b + i * 256,
                                            D, lg, shifted);
        mma_gemm<0><<<dim3(6, nTok / 128), 256, GEMM_SMEM>>>(
            B.a, B.whi + WOFF_QKV(i),
            qkv_b + i * 768, nullptr, B.qh, nTok, 768, 256, 0, 0, 0);
        attn_mma_kernel<<<dim3(nWin, 4), 128, ASMEM>>>(
            B.qh, B.a, rpb + (size_t)i * 2700, D, lg, shifted);
        mma_gemm<1><<<dim3(2, nTok / 128), 256, GEMM_SMEM>>>(
            B.a, B.whi + WOFF_PROJ(i),
            proj_b + i * 256, B.h, nullptr, nTok, 256, 256, D, lg, shifted);
    }
    ln_plain_kernel<<<nTok / 4, 128>>>(B.h, B.a, n2w + i * 256, n2b + i * 256);
    mma_gemm<2><<<dim3(8, nTok / 128), 256, GEMM_SMEM>>>(
        B.a, B.whi + WOFF_MLP1(i),
        mlp1_b + i * 1024, nullptr, B.hid, nTok, 1024, 256, 0, 0, 0);
    if (dual)
        mma_gemm<5><<<dim3(2, nTok / 128), 256, GEMM_SMEM>>>(
            B.hid, B.whi + WOFF_MLP2(i),
            mlp2_b + i * 256, B.h, B.a, nTok, 256, 1024, 0, 0, 0);
    else
        mma_gemm<3><<<dim3(2, nTok / 128), 256, GEMM_SMEM>>>(
            B.hid, B.whi + WOFF_MLP2(i),
            mlp2_b + i * 256, B.h, nullptr, nTok, 256, 1024, 0, 0, 0);
}

extern "C" void kernel_launch(void* const* d_in, const int* in_sizes, int n_in,
                              void* d_out, int out_size)
{
    const float* x       = (const float*)d_in[0];
    const float* n1w     = (const float*)d_in[1];
    const float* n1b     = (const float*)d_in[2];
    const float* qkv_w   = (const float*)d_in[3];
    const float* qkv_b   = (const float*)d_in[4];
    const float* rpb     = (const float*)d_in[5];
    const float* proj_w  = (const float*)d_in[6];
    const float* proj_b  = (const float*)d_in[7];
    const float* n2w     = (const float*)d_in[8];
    const float* n2b     = (const float*)d_in[9];
    const float* mlp1_w  = (const float*)d_in[10];
    const float* mlp1_b  = (const float*)d_in[11];
    const float* mlp2_w  = (const float*)d_in[12];
    const float* mlp2_b  = (const float*)d_in[13];
    const float* exp_v_w = (const float*)d_in[14];
    const float* exp_v_nw= (const float*)d_in[15];
    const float* exp_v_nb= (const float*)d_in[16];
    const float* exp_t_w = (const float*)d_in[17];
    const float* exp_t_nw= (const float*)d_in[18];
    const float* exp_t_nb= (const float*)d_in[19];
    (void)in_sizes; (void)n_in; (void)out_size;

    Bufs B;
    cudaGetSymbolAddress((void**)&B.h,   g_h);
    cudaGetSymbolAddress((void**)&B.a,   g_a);
    cudaGetSymbolAddress((void**)&B.hid, g_hid);
    cudaGetSymbolAddress((void**)&B.qh,  g_qh);
    cudaGetSymbolAddress((void**)&B.whi, g_whi);

    cudaFuncSetAttribute(mma_gemm<0>, cudaFuncAttributeMaxDynamicSharedMemorySize, GEMM_SMEM);
    cudaFuncSetAttribute(mma_gemm<1>, cudaFuncAttributeMaxDynamicSharedMemorySize, GEMM_SMEM);
    cudaFuncSetAttribute(mma_gemm<2>, cudaFuncAttributeMaxDynamicSharedMemorySize, GEMM_SMEM);
    cudaFuncSetAttribute(mma_gemm<3>, cudaFuncAttributeMaxDynamicSharedMemorySize, GEMM_SMEM);
    cudaFuncSetAttribute(mma_gemm<5>, cudaFuncAttributeMaxDynamicSharedMemorySize, GEMM_SMEM);
    cudaFuncSetAttribute(attn_mma_kernel, cudaFuncAttributeMaxDynamicSharedMemorySize, ASMEM);

    // batched weight conversions; qkv GEMM + attention in the profiler window
    wconv_kernel<<<dim3(24, 8, 6), 256>>>(qkv_w,  B.whi + WOFF_QKV(0),  256, 768,  196608);
    wconv_kernel<<<dim3(8,  8, 6), 256>>>(proj_w, B.whi + WOFF_PROJ(0), 256, 256,  65536);
    cudaMemcpyAsync(B.h, x, (size_t)32768 * 256 * sizeof(float),
                    cudaMemcpyDeviceToDevice, 0);
    ln_gather_kernel<<<32768 / 4, 128>>>(B.h, B.a, n1w, n1b, 4, 7, 0);
    mma_gemm<0><<<dim3(6, 32768 / 128), 256, GEMM_SMEM>>>(
        B.a, B.whi + WOFF_QKV(0), qkv_b, nullptr, B.qh, 32768, 768, 256, 0, 0, 0);
    attn_mma_kernel<<<dim3(256, 4), 128, ASMEM>>>(B.qh, B.a, rpb, 4, 7, 0);
    mma_gemm<1><<<dim3(2, 32768 / 128), 256, GEMM_SMEM>>>(
        B.a, B.whi + WOFF_PROJ(0), proj_b, B.h, nullptr, 32768, 256, 256, 4, 7, 0);

    wconv_kernel<<<dim3(32, 8, 6), 256>>>(mlp1_w, B.whi + WOFF_MLP1(0), 256, 1024, 262144);
    wconv_kernel<<<dim3(8, 32, 6), 256>>>(mlp2_w, B.whi + WOFF_MLP2(0), 1024, 256, 262144);
    wconv_kernel<<<dim3(16, 8, 1), 256>>>(exp_v_w, B.whi + WOFF_EXPV, 256, 512, 0);
    wconv_kernel<<<dim3(16, 8, 1), 256>>>(exp_t_w, B.whi + WOFF_EXPT, 256, 512, 0);

    // ---- stage 1: D = 4 (front of block 0 already launched above) ----
    run_block(0, 4, 0, B, n1w, n1b, qkv_b, rpb, proj_b, n2w, n2b, mlp1_b, mlp2_b, true,  false);
    run_block(1, 4, 1, B, n1w, n1b, qkv_b, rpb, proj_b, n2w, n2b, mlp1_b, mlp2_b, false, true);

    // ---- view expand: 32768 -> 65536 (fp16 GEMM out -> fp16 LN in) ----
    mma_gemm<0><<<dim3(4, 32768 / 128), 256, GEMM_SMEM>>>(
        B.a, B.whi + WOFF_EXPV, nullptr, nullptr, B.hid, 32768, 512, 256, 0, 0, 0);
    expand_ln_kernel<<<65536 / 4, 128>>>(B.hid, B.h, exp_v_nw, exp_v_nb, 0, 2, 2, 2);

    // ---- stage 2: D = 8 ----
    run_block(2, 8, 0, B, n1w, n1b, qkv_b, rpb, proj_b, n2w, n2b, mlp1_b, mlp2_b, false, false);
    run_block(3, 8, 1, B, n1w, n1b, qkv_b, rpb, proj_b, n2w, n2b, mlp1_b, mlp2_b, false, true);

    // ---- temporal expand: 65536 -> 131072 ----
    mma_gemm<0><<<dim3(4, 65536 / 128), 256, GEMM_SMEM>>>(
        B.a, B.whi + WOFF_EXPT, nullptr, nullptr, B.hid, 65536, 512, 256, 0, 0, 0);
    expand_ln_kernel<<<131072 / 4, 128>>>(B.hid, B.h, exp_t_nw, exp_t_nb, 1, 2, 2, 4);

    // ---- stage 3: D = 16 ----
    run_block(4, 16, 0, B, n1w, n1b, qkv_b, rpb, proj_b, n2w, n2b, mlp1_b, mlp2_b, false, false);
    run_block(5, 16, 1, B, n1w, n1b, qkv_b, rpb, proj_b, n2w, n2b, mlp1_b, mlp2_b, false, false);

    cudaMemcpyAsync(d_out, B.h, (size_t)131072 * 256 * sizeof(float),
                    cudaMemcpyDeviceToDevice, 0);
}

// round 17
// speedup vs baseline: 1.0852x; 1.0642x over previous
#include <cuda_runtime.h>
#include <cuda_fp16.h>
#include <math.h>
#include <cstdint>

// ===========================================================================
// 3-stage video-Swin decoder. C=256, windows (2,8,8)=128 tokens.
// Dense GEMMs: fp16 HMMA, 128x128 CTA / 32x64 warp tile, BK=64, 3-stage
// cp.async pipeline, 2 CTAs/SM. Attention: plain fp16 HMMA.
// This round: boundary memcpys folded into LN-gather src / mlp2 epilogue.
// ===========================================================================

#define MAXTOK 131072
#define GEMM_SMEM (3 * 32768)

// ---- scratch (static device globals; no runtime allocation allowed) ----
__device__ float g_h  [(size_t)MAXTOK * 256];
__device__ __half g_a  [(size_t)MAXTOK * 256];
__device__ __half g_hid[(size_t)MAXTOK * 1024];   // mlp hidden / expand out
__device__ __half g_qh [(size_t)MAXTOK * 768];

#define WOFF_QKV(i)  ((size_t)(i) * 196608)
#define WOFF_PROJ(i) (1179648u + (size_t)(i) * 65536)
#define WOFF_MLP1(i) (1572864u + (size_t)(i) * 262144)
#define WOFF_MLP2(i) (3145728u + (size_t)(i) * 262144)
#define WOFF_EXPV    4718592u
#define WOFF_EXPT    4849664u
#define WTOT         4980736u
__device__ __half g_whi[WTOT];

// ===========================================================================
// PTX helpers
// ===========================================================================
__device__ __forceinline__ uint32_t smem_u32(const void* p) {
    uint32_t a;
    asm("{ .reg .u64 t; cvta.to.shared.u64 t, %1; cvt.u32.u64 %0, t; }"
        : "=r"(a) : "l"(p));
    return a;
}
__device__ __forceinline__ void cpasync16(uint32_t s, const void* g) {
    asm volatile("cp.async.cg.shared.global [%0], [%1], 16;" :: "r"(s), "l"(g));
}
#define CP_COMMIT() asm volatile("cp.async.commit_group;" ::: "memory")
#define CP_WAIT1()  asm volatile("cp.async.wait_group 1;" ::: "memory")
#define CP_WAIT0()  asm volatile("cp.async.wait_group 0;" ::: "memory")

__device__ __forceinline__ void ldsm4(uint32_t (&r)[4], uint32_t addr) {
    asm volatile("ldmatrix.sync.aligned.m8n8.x4.shared.b16 {%0,%1,%2,%3}, [%4];"
        : "=r"(r[0]), "=r"(r[1]), "=r"(r[2]), "=r"(r[3]) : "r"(addr));
}
__device__ __forceinline__ void ldsm4t(uint32_t (&r)[4], uint32_t addr) {
    asm volatile("ldmatrix.sync.aligned.m8n8.x4.trans.shared.b16 {%0,%1,%2,%3}, [%4];"
        : "=r"(r[0]), "=r"(r[1]), "=r"(r[2]), "=r"(r[3]) : "r"(addr));
}
__device__ __forceinline__ void mma16816(float (&d)[4], const uint32_t (&a)[4],
                                         uint32_t b0, uint32_t b1) {
    asm volatile(
        "mma.sync.aligned.m16n8k16.row.col.f32.f16.f16.f32 "
        "{%0,%1,%2,%3}, {%4,%5,%6,%7}, {%8,%9}, {%0,%1,%2,%3};"
        : "+f"(d[0]), "+f"(d[1]), "+f"(d[2]), "+f"(d[3])
        : "r"(a[0]), "r"(a[1]), "r"(a[2]), "r"(a[3]), "r"(b0), "r"(b1));
}
__device__ __forceinline__ uint32_t SW(uint32_t o) { return o ^ ((o >> 3) & 0x70); }

// ===========================================================================
// misc helpers
// ===========================================================================
__device__ __forceinline__ void st_h2(__half* __restrict__ dst, size_t idx,
                                      float a, float b) {
    *(half2*)(dst + idx) = __floats2half2_rn(a, b);
}
__device__ __forceinline__ void st_h4(__half* __restrict__ dst, size_t idx, float4 v) {
    *(half2*)(dst + idx)     = __floats2half2_rn(v.x, v.y);
    *(half2*)(dst + idx + 2) = __floats2half2_rn(v.z, v.w);
}
__device__ __forceinline__ float gelu_exact(float x) {
    return 0.5f * x * (1.f + erff(x * 0.70710678118654752f));
}

// windowed token -> source row in [B,D,64,64]; lg = log2((D/2)*64)
__device__ __forceinline__ size_t win_src_row(int tok, int D, int lg, int shifted) {
    int loc = tok & 127, win = tok >> 7;
    int ld = loc >> 6, lh = (loc >> 3) & 7, lw = loc & 7;
    int b = win >> lg;
    int wr = win & ((1 << lg) - 1);
    int wd = wr >> 6, wh = (wr >> 3) & 7, ww = wr & 7;
    int gd = wd * 2 + ld, gh = wh * 8 + lh, gw = ww * 8 + lw;
    if (shifted) {
        gd += 1; if (gd >= D) gd -= D;
        gh = (gh + 4) & 63;
        gw = (gw + 4) & 63;
    }
    return ((size_t)(b * D + gd) << 12) + (size_t)(gh << 6) + (size_t)gw;
}

// ===========================================================================
// HMMA GEMM
// OP 0: +bias?, store fp16 (ld=N)
// OP 1: proj: rsrc[scatter] + v -> outf[scatter]
// OP 2: GELU -> fp16 @1024
// OP 3: rsrc + v -> outf (ld=256)
// OP 5: OP3 + fp16 dual-store into oh
// ===========================================================================
__device__ __forceinline__ void load_chunk(
    uint32_t sbs, const __half* __restrict__ A, const __half* __restrict__ W,
    int bm, int bn, int K, int kc, int tid)
{
#pragma unroll
    for (int i = 0; i < 4; ++i) {
        int idx = i * 256 + tid;
        int row = idx >> 3, c = idx & 7;
        uint32_t o = SW((uint32_t)(row * 128 + c * 16));
        cpasync16(sbs + o, A + (size_t)(bm + row) * K + kc * 64 + c * 8);
    }
#pragma unroll
    for (int i = 0; i < 4; ++i) {
        int idx = i * 256 + tid;
        int row = idx >> 3, c = idx & 7;
        uint32_t o = SW((uint32_t)(row * 128 + c * 16));
        cpasync16(sbs + 16384 + o, W + (size_t)(bn + row) * K + kc * 64 + c * 8);
    }
}

template<int OP>
__global__ void __launch_bounds__(256, 2) mma_gemm(
    const __half* __restrict__ A, const __half* __restrict__ W,
    const float* __restrict__ bias, const float* __restrict__ rsrc,
    float* __restrict__ outf, __half* __restrict__ oh,
    int M, int N, int K, int Dd, int lg, int shifted)
{
    extern __shared__ char sm[];
    const uint32_t sb = smem_u32(sm);
    const int tid = threadIdx.x;
    const int lane = tid & 31;
    const int wid = tid >> 5;
    const int warpM = wid >> 1;
    const int warpN = wid & 1;
    const int bm = blockIdx.y * 128;
    const int bn = blockIdx.x * 128;
    const int NC = K >> 6;

    const uint32_t abase = (uint32_t)((warpM * 32 + (lane & 15)) * 128 + (lane >> 4) * 16);
    const uint32_t bbase = (uint32_t)((warpN * 64 + ((lane >> 4) * 8) + (lane & 7)) * 128 +
                                      ((lane >> 3) & 1) * 16);

    float acc[2][8][4];
#pragma unroll
    for (int mt = 0; mt < 2; ++mt)
#pragma unroll
        for (int nt = 0; nt < 8; ++nt)
#pragma unroll
            for (int r = 0; r < 4; ++r) acc[mt][nt][r] = 0.f;

    load_chunk(sb,         A, W, bm, bn, K, 0, tid);
    CP_COMMIT();
    if (NC > 1) load_chunk(sb + 32768, A, W, bm, bn, K, 1, tid);
    CP_COMMIT();

    int st = 0, ls = 2;
    for (int c = 0; c < NC; ++c) {
        CP_WAIT1();
        __syncthreads();
        uint32_t base = sb + st * 32768;
#pragma unroll
        for (int ks = 0; ks < 4; ++ks) {
            uint32_t ah[2][4], bh[8][2];
#pragma unroll
            for (int mt = 0; mt < 2; ++mt)
                ldsm4(ah[mt], base + SW(abase + mt * 2048 + ks * 32));
#pragma unroll
            for (int p = 0; p < 4; ++p) {
                uint32_t t[4];
                ldsm4(t, base + 16384 + SW(bbase + p * 2048 + ks * 32));
                bh[2*p][0] = t[0]; bh[2*p][1] = t[1];
                bh[2*p+1][0] = t[2]; bh[2*p+1][1] = t[3];
            }
#pragma unroll
            for (int mt = 0; mt < 2; ++mt)
#pragma unroll
                for (int nt = 0; nt < 8; ++nt)
                    mma16816(acc[mt][nt], ah[mt], bh[nt][0], bh[nt][1]);
        }
        int nc = c + 2;
        if (nc < NC)
            load_chunk(sb + ls * 32768, A, W, bm, bn, K, nc, tid);
        CP_COMMIT();
        st = (st == 2) ? 0 : st + 1;
        ls = (ls == 2) ? 0 : ls + 1;
    }

    const int lr = lane >> 2;
    const int lc = (lane & 3) * 2;

    float bv[8][2];
    if (bias) {
#pragma unroll
        for (int nt = 0; nt < 8; ++nt) {
            int col = bn + warpN * 64 + nt * 8 + lc;
            bv[nt][0] = bias[col];
            bv[nt][1] = bias[col + 1];
        }
    } else {
#pragma unroll
        for (int nt = 0; nt < 8; ++nt) { bv[nt][0] = 0.f; bv[nt][1] = 0.f; }
    }

#pragma unroll
    for (int mt = 0; mt < 2; ++mt) {
        int r0 = bm + warpM * 32 + mt * 16 + lr;
        int r1 = r0 + 8;
        size_t ob0, ob1;
        if (OP == 1) {
            ob0 = win_src_row(r0, Dd, lg, shifted) * 256;
            ob1 = win_src_row(r1, Dd, lg, shifted) * 256;
        } else if (OP == 2) {
            ob0 = (size_t)r0 * 1024; ob1 = (size_t)r1 * 1024;
        } else if (OP == 3 || OP == 5) {
            ob0 = (size_t)r0 * 256;  ob1 = (size_t)r1 * 256;
        } else {
            ob0 = (size_t)r0 * N;    ob1 = (size_t)r1 * N;
        }
#pragma unroll
        for (int nt = 0; nt < 8; ++nt) {
            int col = bn + warpN * 64 + nt * 8 + lc;
            float v0 = acc[mt][nt][0] + bv[nt][0];
            float v1 = acc[mt][nt][1] + bv[nt][1];
            float v2 = acc[mt][nt][2] + bv[nt][0];
            float v3 = acc[mt][nt][3] + bv[nt][1];
            if (OP == 0) {
                st_h2(oh, ob0 + col, v0, v1);
                st_h2(oh, ob1 + col, v2, v3);
            } else if (OP == 1 || OP == 3 || OP == 5) {
                float2 o0 = *(const float2*)(rsrc + ob0 + col);
                o0.x += v0; o0.y += v1;
                *(float2*)(outf + ob0 + col) = o0;
                float2 o1 = *(const float2*)(rsrc + ob1 + col);
                o1.x += v2; o1.y += v3;
                *(float2*)(outf + ob1 + col) = o1;
                if (OP == 5) {
                    st_h2(oh, ob0 + col, o0.x, o0.y);
                    st_h2(oh, ob1 + col, o1.x, o1.y);
                }
            } else {
                st_h2(oh, ob0 + col, gelu_exact(v0), gelu_exact(v1));
                st_h2(oh, ob1 + col, gelu_exact(v2), gelu_exact(v3));
            }
        }
    }
}

// ===========================================================================
// HMMA window attention, plain fp16 (128 threads, 4 warps)
// ===========================================================================
#define ASMEM 53248
#define A_Q  4096
#define A_K  20480
#define A_P0 4096
#define A_P1 20480
#define A_V  36864

__global__ void __launch_bounds__(128, 2) attn_mma_kernel(
    const __half* __restrict__ qkv, __half* __restrict__ out,
    const float* __restrict__ rpb, int D, int lg, int shifted)
{
    extern __shared__ char smc[];
    const uint32_t sb = smem_u32(smc);
    const int tid = threadIdx.x;
    const int lane = tid & 31;
    const int wid = tid >> 5;
    const int wbase = wid * 32;
    const int win = blockIdx.x;
    const int head = blockIdx.y;
    const size_t tokBase = (size_t)win * 128;

    float* rpbs = (float*)smc;
    int* clut = (int*)(smc + 2704);

    {
        const __half* ph = qkv + tokBase * 768 + head * 64;
#pragma unroll
        for (int i = 0; i < 8; ++i) {
            int idx = i * 128 + tid;
            int r = idx >> 3, c = idx & 7;
            uint32_t o = SW((uint32_t)(r * 128 + c * 16));
            size_t g = (size_t)r * 768 + c * 8;
            cpasync16(sb + A_Q + o, ph + g);
            cpasync16(sb + A_K + o, ph + 256 + g);
        }
        CP_COMMIT();
#pragma unroll
        for (int i = 0; i < 8; ++i) {
            int idx = i * 128 + tid;
            int r = idx >> 3, c = idx & 7;
            uint32_t o = SW((uint32_t)(r * 128 + c * 16));
            size_t g = (size_t)r * 768 + c * 8;
            cpasync16(sb + A_V + o, ph + 512 + g);
        }
        CP_COMMIT();
    }

    for (int i = tid; i < 675; i += 128) rpbs[i] = rpb[i * 4 + head];
    {
        int p = tid;
        int ld = p >> 6, lh = (p >> 3) & 7, lw = p & 7;
        int ct = ld * 225 + lh * 15 + lw;
        int wr = win & ((1 << lg) - 1);
        int wd = wr >> 6, wh = (wr >> 3) & 7, ww = wr & 7;
        int gd = wd * 2 + ld, gh2 = wh * 8 + lh, gw2 = ww * 8 + lw;
        int rd = (gd < D - 2) ? 0 : ((gd < D - 1) ? 1 : 2);
        int rh = (gh2 < 56) ? 0 : ((gh2 < 60) ? 1 : 2);
        int rw = (gw2 < 56) ? 0 : ((gw2 < 60) ? 1 : 2);
        clut[p] = ct | ((rd * 9 + rh * 3 + rw) << 16);
    }

    CP_WAIT1();
    __syncthreads();

    // ---- phase 1: S = q k^T ----
    float acc[2][16][4];
#pragma unroll
    for (int mt = 0; mt < 2; ++mt)
#pragma unroll
        for (int nt = 0; nt < 16; ++nt)
#pragma unroll
            for (int r = 0; r < 4; ++r) acc[mt][nt][r] = 0.f;

#pragma unroll
    for (int ks = 0; ks < 4; ++ks) {
        uint32_t aQ[2][4];
#pragma unroll
        for (int mt = 0; mt < 2; ++mt) {
            uint32_t o = (uint32_t)((wbase + mt * 16 + (lane & 15)) * 128 +
                                    ks * 32 + (lane >> 4) * 16);
            ldsm4(aQ[mt], sb + A_Q + SW(o));
        }
#pragma unroll
        for (int p4 = 0; p4 < 8; ++p4) {
            uint32_t o = (uint32_t)((p4 * 16 + (lane >> 4) * 8 + (lane & 7)) * 128 +
                                    ks * 32 + ((lane >> 3) & 1) * 16);
            uint32_t th[4];
            ldsm4(th, sb + A_K + SW(o));
#pragma unroll
            for (int mt = 0; mt < 2; ++mt) {
                mma16816(acc[mt][2*p4],   aQ[mt], th[0], th[1]);
                mma16816(acc[mt][2*p4+1], aQ[mt], th[2], th[3]);
            }
        }
    }

    // ---- bias + mask + softmax ----
    const int lr = lane >> 2;
    const int lc = lane & 3;
    int clv[16][2];
#pragma unroll
    for (int nt = 0; nt < 16; ++nt) {
        clv[nt][0] = clut[nt * 8 + lc * 2];
        clv[nt][1] = clut[nt * 8 + lc * 2 + 1];
    }
    float inv[4];
#pragma unroll
    for (int ri = 0; ri < 4; ++ri) {
        int mt = ri >> 1, hh = ri & 1;
        int row = wbase + mt * 16 + hh * 8 + lr;
        int rv = clut[row];
        int basep = (rv & 0xffff) + 337;
        int rlab = rv >> 16;
        float mx = -1e30f;
#pragma unroll
        for (int nt = 0; nt < 16; ++nt)
#pragma unroll
            for (int e = 0; e < 2; ++e) {
                float s = acc[mt][nt][hh * 2 + e] * 0.125f +
                          rpbs[basep - (clv[nt][e] & 0xffff)];
                if (shifted && ((clv[nt][e] >> 16) != rlab)) s -= 100.f;
                acc[mt][nt][hh * 2 + e] = s;
                mx = fmaxf(mx, s);
            }
        mx = fmaxf(mx, __shfl_xor_sync(0xffffffffu, mx, 1));
        mx = fmaxf(mx, __shfl_xor_sync(0xffffffffu, mx, 2));
        float sr = 0.f;
#pragma unroll
        for (int nt = 0; nt < 16; ++nt)
#pragma unroll
            for (int e = 0; e < 2; ++e) {
                float p = __expf(acc[mt][nt][hh * 2 + e] - mx);
                acc[mt][nt][hh * 2 + e] = p;
                sr += p;
            }
        sr += __shfl_xor_sync(0xffffffffu, sr, 1);
        sr += __shfl_xor_sync(0xffffffffu, sr, 2);
        inv[ri] = 1.f / sr;
    }

    __syncthreads();   // phase-1 smem reads done; P aliases Q/K region

#pragma unroll
    for (int ri = 0; ri < 4; ++ri) {
        int mt = ri >> 1, hh = ri & 1;
        int row = wbase + mt * 16 + hh * 8 + lr;
#pragma unroll
        for (int nt = 0; nt < 16; ++nt) {
            float p0 = acc[mt][nt][hh * 2];
            float p1 = acc[mt][nt][hh * 2 + 1];
            uint32_t off = SW((uint32_t)(row * 128 + ((nt & 7) * 8 + lc * 2) * 2));
            uint32_t pbase = (nt < 8) ? A_P0 : A_P1;
            *(half2*)(smc + pbase + off) = __floats2half2_rn(p0, p1);
        }
    }
    CP_WAIT0();
    __syncthreads();

    // ---- phase 2: O = P V ----
    float oa[2][8][4];
#pragma unroll
    for (int mt = 0; mt < 2; ++mt)
#pragma unroll
        for (int nt = 0; nt < 8; ++nt)
#pragma unroll
            for (int r = 0; r < 4; ++r) oa[mt][nt][r] = 0.f;

#pragma unroll
    for (int kc = 0; kc < 2; ++kc)
#pragma unroll
        for (int ks = 0; ks < 4; ++ks) {
            uint32_t aP[2][4];
#pragma unroll
            for (int mt = 0; mt < 2; ++mt) {
                uint32_t o = (uint32_t)((wbase + mt * 16 + (lane & 15)) * 128 +
                                        ks * 32 + (lane >> 4) * 16);
                ldsm4(aP[mt], sb + (kc ? A_P1 : A_P0) + SW(o));
            }
#pragma unroll
            for (int p4 = 0; p4 < 4; ++p4) {
                uint32_t o = (uint32_t)((kc * 64 + ks * 16 + (lane & 15)) * 128 +
                                        p4 * 32 + (lane >> 4) * 16);
                uint32_t th[4];
                ldsm4t(th, sb + A_V + SW(o));
#pragma unroll
                for (int mt = 0; mt < 2; ++mt) {
                    mma16816(oa[mt][2*p4],   aP[mt], th[0], th[1]);
                    mma16816(oa[mt][2*p4+1], aP[mt], th[2], th[3]);
                }
            }
        }

#pragma unroll
    for (int ri = 0; ri < 4; ++ri) {
        int mt = ri >> 1, hh = ri & 1;
        int row = wbase + mt * 16 + hh * 8 + lr;
        size_t ob = (tokBase + row) * 256 + head * 64;
#pragma unroll
        for (int nt = 0; nt < 8; ++nt) {
            float v0 = oa[mt][nt][hh * 2] * inv[ri];
            float v1 = oa[mt][nt][hh * 2 + 1] * inv[ri];
            st_h2(out, ob + nt * 8 + lc * 2, v0, v1);
        }
    }
}

// ===========================================================================
// Batched weight transpose; LayerNorms
// ===========================================================================
__global__ void __launch_bounds__(256) wconv_kernel(
    const float* __restrict__ W, __half* __restrict__ hi, int K, int N,
    size_t stride)
{
    W  += (size_t)blockIdx.z * stride;
    hi += (size_t)blockIdx.z * stride;
    __shared__ float t[32][33];
    int n0 = blockIdx.x * 32, k0 = blockIdx.y * 32;
    int tx = threadIdx.x & 31, ty = threadIdx.x >> 5;
    for (int i = ty; i < 32; i += 8)
        t[i][tx] = W[(size_t)(k0 + i) * N + n0 + tx];
    __syncthreads();
    for (int i = ty; i < 32; i += 8)
        hi[(size_t)(n0 + i) * K + k0 + tx] = __float2half_rn(t[tx][i]);
}

__device__ __forceinline__ void warp_ln_vals(
    float4 v0, float4 v1, const float* __restrict__ gw,
    const float* __restrict__ gb, int lane, float4& r0, float4& r1)
{
    float s = v0.x + v0.y + v0.z + v0.w + v1.x + v1.y + v1.z + v1.w;
    float q = v0.x*v0.x + v0.y*v0.y + v0.z*v0.z + v0.w*v0.w +
              v1.x*v1.x + v1.y*v1.y + v1.z*v1.z + v1.w*v1.w;
#pragma unroll
    for (int off = 16; off; off >>= 1) {
        s += __shfl_xor_sync(0xffffffffu, s, off);
        q += __shfl_xor_sync(0xffffffffu, q, off);
    }
    float mu = s * (1.f / 256.f);
    float var = q * (1.f / 256.f) - mu * mu;
    float rs = rsqrtf(var + 1e-5f);
    const float4* g4 = (const float4*)gw;
    const float4* b4 = (const float4*)gb;
    float4 g0 = g4[lane], g1 = g4[lane + 32];
    float4 c0 = b4[lane], c1 = b4[lane + 32];
    r0.x = (v0.x - mu) * rs * g0.x + c0.x;
    r0.y = (v0.y - mu) * rs * g0.y + c0.y;
    r0.z = (v0.z - mu) * rs * g0.z + c0.z;
    r0.w = (v0.w - mu) * rs * g0.w + c0.w;
    r1.x = (v1.x - mu) * rs * g1.x + c1.x;
    r1.y = (v1.y - mu) * rs * g1.y + c1.y;
    r1.z = (v1.z - mu) * rs * g1.z + c1.z;
    r1.w = (v1.w - mu) * rs * g1.w + c1.w;
}

__global__ void __launch_bounds__(128) ln_gather_kernel(
    const float* __restrict__ h, __half* __restrict__ o,
    const float* __restrict__ gw, const float* __restrict__ gb,
    int D, int lg, int shifted)
{
    int tok = (blockIdx.x << 2) + (threadIdx.x >> 5);
    int lane = threadIdx.x & 31;
    const float4* xin = (const float4*)(h + win_src_row(tok, D, lg, shifted) * 256);
    float4 r0, r1;
    warp_ln_vals(xin[lane], xin[lane + 32], gw, gb, lane, r0, r1);
    size_t ob = (size_t)tok * 256 + lane * 4;
    st_h4(o, ob, r0);
    st_h4(o, ob + 128, r1);
}

__global__ void __launch_bounds__(128) ln_plain_kernel(
    const float* __restrict__ h, __half* __restrict__ o,
    const float* __restrict__ gw, const float* __restrict__ gb)
{
    int tok = (blockIdx.x << 2) + (threadIdx.x >> 5);
    int lane = threadIdx.x & 31;
    const float4* xin = (const float4*)(h + (size_t)tok * 256);
    float4 r0, r1;
    warp_ln_vals(xin[lane], xin[lane + 32], gw, gb, lane, r0, r1);
    size_t ob = (size_t)tok * 256 + lane * 4;
    st_h4(o, ob, r0);
    st_h4(o, ob + 128, r1);
}

// expand reorder + LN; src is fp16 (expand GEMM output @ld=512), dst fp32 h
__global__ void __launch_bounds__(128) expand_ln_kernel(
    const __half* __restrict__ src, float* __restrict__ dst,
    const float* __restrict__ gw, const float* __restrict__ gb,
    int mode, int B, int T, int V)
{
    int tok = (blockIdx.x << 2) + (threadIdx.x >> 5);
    int lane = threadIdx.x & 31;
    int l = tok & 4095;
    int r = tok >> 12;
    int srow, e;
    if (mode == 0) {
        int V2 = V * 2;
        int v2 = r % V2; r /= V2;
        int t = r % T;   int b = r / T;
        e = v2 & 1;
        srow = ((b * T + t) * V + (v2 >> 1)) * 4096 + l;
    } else {
        int vv = r % V;  r /= V;
        int T2 = T * 2;
        int t2 = r % T2; int b = r / T2;
        e = t2 & 1;
        srow = ((b * T + (t2 >> 1)) * V + vv) * 4096 + l;
    }
    const __half* s = src + (size_t)srow * 512 + e * 256;
    float4 v0, v1;
    {
        half2 a0 = *(const half2*)(s + lane * 4);
        half2 a1 = *(const half2*)(s + lane * 4 + 2);
        half2 b0 = *(const half2*)(s + 128 + lane * 4);
        half2 b1 = *(const half2*)(s + 128 + lane * 4 + 2);
        v0 = make_float4(__half2float(a0.x), __half2float(a0.y),
                         __half2float(a1.x), __half2float(a1.y));
        v1 = make_float4(__half2float(b0.x), __half2float(b0.y),
                         __half2float(b1.x), __half2float(b1.y));
    }
    float4 r0, r1;
    warp_ln_vals(v0, v1, gw, gb, lane, r0, r1);
    float4* o = (float4*)(dst + (size_t)tok * 256);
    o[lane] = r0;
    o[lane + 32] = r1;
}

// ===========================================================================
// Host orchestration
// ===========================================================================
struct Bufs {
    float *h;
    __half *a, *hid, *qh, *whi;
};

static inline int lg2_nwinb(int D) { return (D == 4) ? 7 : (D == 8) ? 8 : 9; }

// hsrc: residual/LN source for the front (x for block 0, h otherwise)
// hout: mlp2 residual write target (d_out for the final block, h otherwise)
static void run_block(int i, int D, int shifted, const Bufs& B,
                      const float* hsrc, float* hout,
                      const float* n1w, const float* n1b,
                      const float* qkv_b, const float* rpb,
                      const float* proj_b, const float* n2w, const float* n2b,
                      const float* mlp1_b, const float* mlp2_b,
                      bool skip_front, bool dual)
{
    const int nTok = 2 * D * 4096;
    const int nWin = nTok / 128;
    const int lg = lg2_nwinb(D);

    if (!skip_front) {
        ln_gather_kernel<<<nTok / 4, 128>>>(hsrc, B.a, n1w + i * 256, n1b + i * 256,
                                            D, lg, shifted);
        mma_gemm<0><<<dim3(6, nTok / 128), 256, GEMM_SMEM>>>(
            B.a, B.whi + WOFF_QKV(i),
            qkv_b + i * 768, nullptr, nullptr, B.qh, nTok, 768, 256, 0, 0, 0);
        attn_mma_kernel<<<dim3(nWin, 4), 128, ASMEM>>>(
            B.qh, B.a, rpb + (size_t)i * 2700, D, lg, shifted);
        mma_gemm<1><<<dim3(2, nTok / 128), 256, GEMM_SMEM>>>(
            B.a, B.whi + WOFF_PROJ(i),
            proj_b + i * 256, hsrc, B.h, nullptr, nTok, 256, 256, D, lg, shifted);
    }
    ln_plain_kernel<<<nTok / 4, 128>>>(B.h, B.a, n2w + i * 256, n2b + i * 256);
    mma_gemm<2><<<dim3(8, nTok / 128), 256, GEMM_SMEM>>>(
        B.a, B.whi + WOFF_MLP1(i),
        mlp1_b + i * 1024, nullptr, nullptr, B.hid, nTok, 1024, 256, 0, 0, 0);
    if (dual)
        mma_gemm<5><<<dim3(2, nTok / 128), 256, GEMM_SMEM>>>(
            B.hid, B.whi + WOFF_MLP2(i),
            mlp2_b + i * 256, B.h, hout, B.a, nTok, 256, 1024, 0, 0, 0);
    else
        mma_gemm<3><<<dim3(2, nTok / 128), 256, GEMM_SMEM>>>(
            B.hid, B.whi + WOFF_MLP2(i),
            mlp2_b + i * 256, B.h, hout, nullptr, nTok, 256, 1024, 0, 0, 0);
}

extern "C" void kernel_launch(void* const* d_in, const int* in_sizes, int n_in,
                              void* d_out, int out_size)
{
    const float* x       = (const float*)d_in[0];
    const float* n1w     = (const float*)d_in[1];
    const float* n1b     = (const float*)d_in[2];
    const float* qkv_w   = (const float*)d_in[3];
    const float* qkv_b   = (const float*)d_in[4];
    const float* rpb     = (const float*)d_in[5];
    const float* proj_w  = (const float*)d_in[6];
    const float* proj_b  = (const float*)d_in[7];
    const float* n2w     = (const float*)d_in[8];
    const float* n2b     = (const float*)d_in[9];
    const float* mlp1_w  = (const float*)d_in[10];
    const float* mlp1_b  = (const float*)d_in[11];
    const float* mlp2_w  = (const float*)d_in[12];
    const float* mlp2_b  = (const float*)d_in[13];
    const float* exp_v_w = (const float*)d_in[14];
    const float* exp_v_nw= (const float*)d_in[15];
    const float* exp_v_nb= (const float*)d_in[16];
    const float* exp_t_w = (const float*)d_in[17];
    const float* exp_t_nw= (const float*)d_in[18];
    const float* exp_t_nb= (const float*)d_in[19];
    (void)in_sizes; (void)n_in; (void)out_size;
    float* outp = (float*)d_out;

    Bufs B;
    cudaGetSymbolAddress((void**)&B.h,   g_h);
    cudaGetSymbolAddress((void**)&B.a,   g_a);
    cudaGetSymbolAddress((void**)&B.hid, g_hid);
    cudaGetSymbolAddress((void**)&B.qh,  g_qh);
    cudaGetSymbolAddress((void**)&B.whi, g_whi);

    cudaFuncSetAttribute(mma_gemm<0>, cudaFuncAttributeMaxDynamicSharedMemorySize, GEMM_SMEM);
    cudaFuncSetAttribute(mma_gemm<1>, cudaFuncAttributeMaxDynamicSharedMemorySize, GEMM_SMEM);
    cudaFuncSetAttribute(mma_gemm<2>, cudaFuncAttributeMaxDynamicSharedMemorySize, GEMM_SMEM);
    cudaFuncSetAttribute(mma_gemm<3>, cudaFuncAttributeMaxDynamicSharedMemorySize, GEMM_SMEM);
    cudaFuncSetAttribute(mma_gemm<5>, cudaFuncAttributeMaxDynamicSharedMemorySize, GEMM_SMEM);
    cudaFuncSetAttribute(attn_mma_kernel, cudaFuncAttributeMaxDynamicSharedMemorySize, ASMEM);

    // batched weight conversions; qkv GEMM + attention in the profiler window
    wconv_kernel<<<dim3(24, 8, 6), 256>>>(qkv_w,  B.whi + WOFF_QKV(0),  256, 768,  196608);
    wconv_kernel<<<dim3(8,  8, 6), 256>>>(proj_w, B.whi + WOFF_PROJ(0), 256, 256,  65536);
    ln_gather_kernel<<<32768 / 4, 128>>>(x, B.a, n1w, n1b, 4, 7, 0);
    mma_gemm<0><<<dim3(6, 32768 / 128), 256, GEMM_SMEM>>>(
        B.a, B.whi + WOFF_QKV(0), qkv_b, nullptr, nullptr, B.qh, 32768, 768, 256, 0, 0, 0);
    attn_mma_kernel<<<dim3(256, 4), 128, ASMEM>>>(B.qh, B.a, rpb, 4, 7, 0);
    mma_gemm<1><<<dim3(2, 32768 / 128), 256, GEMM_SMEM>>>(
        B.a, B.whi + WOFF_PROJ(0), proj_b, x, B.h, nullptr, 32768, 256, 256, 4, 7, 0);

    wconv_kernel<<<dim3(32, 8, 6), 256>>>(mlp1_w, B.whi + WOFF_MLP1(0), 256, 1024, 262144);
    wconv_kernel<<<dim3(8, 32, 6), 256>>>(mlp2_w, B.whi + WOFF_MLP2(0), 1024, 256, 262144);
    wconv_kernel<<<dim3(16, 8, 1), 256>>>(exp_v_w, B.whi + WOFF_EXPV, 256, 512, 0);
    wconv_kernel<<<dim3(16, 8, 1), 256>>>(exp_t_w, B.whi + WOFF_EXPT, 256, 512, 0);

    // ---- stage 1: D = 4 (front of block 0 already launched above) ----
    run_block(0, 4, 0, B, B.h, B.h, n1w, n1b, qkv_b, rpb, proj_b, n2w, n2b,
              mlp1_b, mlp2_b, true,  false);
    run_block(1, 4, 1, B, B.h, B.h, n1w, n1b, qkv_b, rpb, proj_b, n2w, n2b,
              mlp1_b, mlp2_b, false, true);

    // ---- view expand: 32768 -> 65536 (fp16 GEMM out -> fp16 LN in) ----
    mma_gemm<0><<<dim3(4, 32768 / 128), 256, GEMM_SMEM>>>(
        B.a, B.whi + WOFF_EXPV, nullptr, nullptr, nullptr, B.hid, 32768, 512, 256, 0, 0, 0);
    expand_ln_kernel<<<65536 / 4, 128>>>(B.hid, B.h, exp_v_nw, exp_v_nb, 0, 2, 2, 2);

    // ---- stage 2: D = 8 ----
    run_block(2, 8, 0, B, B.h, B.h, n1w, n1b, qkv_b, rpb, proj_b, n2w, n2b,
              mlp1_b, mlp2_b, false, false);
    run_block(3, 8, 1, B, B.h, B.h, n1w, n1b, qkv_b, rpb, proj_b, n2w, n2b,
              mlp1_b, mlp2_b, false, true);

    // ---- temporal expand: 65536 -> 131072 ----
    mma_gemm<0><<<dim3(4, 65536 / 128), 256, GEMM_SMEM>>>(
        B.a, B.whi + WOFF_EXPT, nullptr, nullptr, nullptr, B.hid, 65536, 512, 256, 0, 0, 0);
    expand_ln_kernel<<<131072 / 4, 128>>>(B.hid, B.h, exp_t_nw, exp_t_nb, 1, 2, 2, 4);

    // ---- stage 3: D = 16; final mlp2 writes straight into d_out ----
    run_block(4, 16, 0, B, B.h, B.h, n1w, n1b, qkv_b, rpb, proj_b, n2w, n2b,
              mlp1_b, mlp2_b, false, false);
    run_block(5, 16, 1, B, B.h, outp, n1w, n1b, qkv_b, rpb, proj_b, n2w, n2b,
              mlp1_b, mlp2_b, false, false);
}